// round 14
// baseline (speedup 1.0000x reference)
#include <cuda_runtime.h>
#include <cuda_fp16.h>
#include <math.h>
#include <stdint.h>

#define B_  2
#define S_  512
#define V_  32000
#define D_  768
#define F_  2048
#define L_  4
#define H_  12
#define HD_ 64
#define FCS_ 8
#define YW_ (S_ + FCS_ - 1)   /* 519 */
#define NT_ (B_ * S_)         /* 1024 rows */

// ---------------- static scratch (allocation-free rule) ----------------
__device__ float  g_h [NT_ * D_];
__device__ float  g_q [NT_ * D_];
__device__ float  g_k [NT_ * D_];
__device__ float  g_v [NT_ * D_];
__device__ float  g_g1[NT_ * F_];
__device__ float  g_c [NT_ * V_];          // context head logits c (131 MB)
__device__ float2 g_rope[S_ * 32];
__device__ double g_acc[4];                // [0]=softplus [1]=delta [2]=nll [3]=valid
__device__ float  g_rowsum[NT_];           // per-row sum exp(logit-20)

// fp16 activations (hi + lo residual where needed)
__device__ __align__(16) __half g_ah[NT_ * D_], g_al[NT_ * D_];
__device__ __align__(16) __half g_oh[NT_ * D_];
__device__ __align__(16) __half g_uh[NT_ * F_], g_ul[NT_ * F_];

// fp16 weights (converted once per launch)
__device__ __align__(16) __half g_wq[L_*D_*D_];
__device__ __align__(16) __half g_wk[L_*D_*D_];
__device__ __align__(16) __half g_wv[L_*D_*D_];
__device__ __align__(16) __half g_wo[L_*D_*D_];
__device__ __align__(16) __half g_w1[L_*F_*D_];
__device__ __align__(16) __half g_w3[L_*F_*D_];
__device__ __align__(16) __half g_w2[L_*D_*F_];
__device__ __align__(16) __half g_wout[V_*D_];
__device__ __align__(16) __half g_wctx[V_*D_];

__device__ __forceinline__ float softplusf(float x) {
    if (x > 15.0f) return x;
    return log1pf(expf(x));
}

__device__ __forceinline__ void mma_f16(float& c0, float& c1, float& c2, float& c3,
                                        uint32_t a0, uint32_t a1, uint32_t a2, uint32_t a3,
                                        uint32_t b0, uint32_t b1) {
    asm volatile("mma.sync.aligned.m16n8k16.row.col.f32.f16.f16.f32 "
                 "{%0,%1,%2,%3}, {%4,%5,%6,%7}, {%8,%9}, {%0,%1,%2,%3};"
                 : "+f"(c0), "+f"(c1), "+f"(c2), "+f"(c3)
                 : "r"(a0), "r"(a1), "r"(a2), "r"(a3), "r"(b0), "r"(b1));
}

// ---------------- ALL weight converts in one launch (grid-stride) ----------------
__global__ void wconv_all(const float* __restrict__ wq, const float* __restrict__ wk,
                          const float* __restrict__ wv, const float* __restrict__ wo,
                          const float* __restrict__ w1, const float* __restrict__ w3,
                          const float* __restrict__ w2,
                          const float* __restrict__ wout, const float* __restrict__ wctx) {
    constexpr long DD4 = (long)L_ * D_ * D_ / 4;
    constexpr long FD4 = (long)L_ * F_ * D_ / 4;
    constexpr long VD4 = (long)V_ * D_ / 4;
    constexpr long E0 = 4 * DD4, E1 = E0 + 3 * FD4, TOT = E1 + 2 * VD4;
    const long stride = (long)gridDim.x * blockDim.x;
    for (long i = (long)blockIdx.x * blockDim.x + threadIdx.x; i < TOT; i += stride) {
        const float* src; __half* dst; long off;
        if (i < E0) {
            int seg = (int)(i / DD4); off = i - (long)seg * DD4;
            src = (seg == 0) ? wq : (seg == 1) ? wk : (seg == 2) ? wv : wo;
            dst = (seg == 0) ? g_wq : (seg == 1) ? g_wk : (seg == 2) ? g_wv : g_wo;
        } else if (i < E1) {
            long j = i - E0; int seg = (int)(j / FD4); off = j - (long)seg * FD4;
            src = (seg == 0) ? w1 : (seg == 1) ? w3 : w2;
            dst = (seg == 0) ? g_w1 : (seg == 1) ? g_w3 : g_w2;
        } else {
            long j = i - E1; int seg = (int)(j / VD4); off = j - (long)seg * VD4;
            src = (seg == 0) ? wout : wctx;
            dst = (seg == 0) ? g_wout : g_wctx;
        }
        float4 v = ((const float4*)src)[off];
        ((__half2*)dst)[2 * off]     = __floats2half2_rn(v.x, v.y);
        ((__half2*)dst)[2 * off + 1] = __floats2half2_rn(v.z, v.w);
    }
}

// ---------------- embedding gather (+ acc/rowsum zero + rope table) ----------
__global__ void embed_kernel(const int* __restrict__ x, const float* __restrict__ emb) {
    int i = blockIdx.x * blockDim.x + threadIdx.x;
    if (i < 4) g_acc[i] = 0.0;
    if (i < NT_) g_rowsum[i] = 0.f;
    if (i < S_ * 32) {
        int s = i / 32, p = i - (i / 32) * 32;
        float f   = expf((float)(2 * p) * (-logf(10000.0f) / (float)HD_));
        float ang = (float)s * f;
        double a  = (double)ang;
        g_rope[i] = make_float2((float)cos(a), (float)sin(a));
    }
    if (i >= NT_ * D_) return;
    int row = i / D_;
    int d   = i - row * D_;
    g_h[i] = emb[(size_t)x[row] * D_ + d];
}

// ---------------- rmsnorm (SPLIT: 1=fp16 hi only, 2=fp16 hi+lo) ----------------
template<int SPLIT>
__global__ void rmsnorm_kernel(const float* __restrict__ in, const float* __restrict__ w,
                               __half* __restrict__ oh, __half* __restrict__ ol) {
    int row = blockIdx.x;
    const float* ip = in + row * D_;
    __shared__ float red[256];
    float ss = 0.f;
    for (int d = threadIdx.x; d < D_; d += 256) { float v = ip[d]; ss += v * v; }
    red[threadIdx.x] = ss; __syncthreads();
    for (int st = 128; st > 0; st >>= 1) {
        if (threadIdx.x < st) red[threadIdx.x] += red[threadIdx.x + st];
        __syncthreads();
    }
    float rs = rsqrtf(red[0] / (float)D_ + 1e-5f);
    for (int d = threadIdx.x; d < D_; d += 256) {
        float v = ip[d] * rs * w[d];
        __half h = __float2half_rn(v);
        oh[row * D_ + d] = h;
        if (SPLIT == 2) ol[row * D_ + d] = __float2half_rn(v - __half2float(h));
    }
}

#define TLD 20   /* smem row stride (u32): fragment loads conflict-free */

// =======================================================================
//  fp16 NT-GEMM:  C[m,n] (op)= sum_k A[m,k]*W[n,k]
//  NI=1: A=hi only (1 mma/k16).  NI=2: A=hi+lo residual (2 mma/k16).
//  EPI: 0=store 1=add 2=silu 3=mulG->fp16 hi/lo 4=store+softplus 5=rope-store
// =======================================================================
template<int BM, int BN, int WM, int WN, int EPI, int NI>
__device__ __forceinline__ void gemm_f16_core(const __half* __restrict__ Ah,
                                              const __half* __restrict__ Al,
                                              const __half* __restrict__ Bw,
                                              float* __restrict__ C,
                                              const float* __restrict__ G,
                                              __half* __restrict__ Oh,
                                              __half* __restrict__ Ol,
                                              int N, int K, int bm, int bn) {
    constexpr int THREADS = WM * WN * 32;
    constexpr int WTM = BM / WM;
    constexpr int WTN = BN / WN;
    constexpr int MT  = WTM / 16;
    constexpr int NTT = WTN / 8;
    constexpr int RPP = THREADS / 2;
    constexpr int NLA = BM / RPP;
    constexpr int NLB = BN / RPP;

    __shared__ uint32_t As[2][BM][TLD];
    __shared__ uint32_t Bs[2][BN][TLD];
    __shared__ float sred[THREADS];

    const int tid  = threadIdx.x;
    const int lane = tid & 31;
    const int wid  = tid >> 5;
    const int wm   = wid / WN;
    const int wn   = wid % WN;

    const int lr = tid >> 1;
    const int ks = (tid & 1) * 8;   // element offset 0/8 in k16 chunk
    const int js = ks >> 1;         // u32 pair offset 0/4
    const __half* Agh = Ah + (size_t)(bm + lr) * K + ks;
    const __half* Agl = (NI == 2) ? Al + (size_t)(bm + lr) * K + ks : nullptr;
    const __half* Bg  = Bw + (size_t)(bn + lr) * K + ks;

    float acc[MT][NTT][4];
#pragma unroll
    for (int i = 0; i < MT; i++)
#pragma unroll
        for (int j = 0; j < NTT; j++)
#pragma unroll
            for (int q = 0; q < 4; q++) acc[i][j][q] = 0.f;

    uint4 pah[NLA], pal[NLA], pbh[NLB];

#pragma unroll
    for (int l = 0; l < NLA; l++) {
        pah[l] = *(const uint4*)(Agh + (size_t)l * RPP * K);
        if (NI == 2) pal[l] = *(const uint4*)(Agl + (size_t)l * RPP * K);
    }
#pragma unroll
    for (int l = 0; l < NLB; l++)
        pbh[l] = *(const uint4*)(Bg + (size_t)l * RPP * K);

    auto store_tiles = [&](int buf) {
#pragma unroll
        for (int l = 0; l < NLA; l++) {
            *(uint4*)&As[buf][lr + l * RPP][js] = pah[l];
            if (NI == 2) *(uint4*)&As[buf][lr + l * RPP][8 + js] = pal[l];
        }
#pragma unroll
        for (int l = 0; l < NLB; l++)
            *(uint4*)&Bs[buf][lr + l * RPP][js] = pbh[l];
    };

    store_tiles(0);
    __syncthreads();

    const int nk = K / 16;
    for (int kc = 0; kc < nk; kc++) {
        const int cur = kc & 1;
        if (kc + 1 < nk) {
            const int off = (kc + 1) * 16;
#pragma unroll
            for (int l = 0; l < NLA; l++) {
                pah[l] = *(const uint4*)(Agh + (size_t)l * RPP * K + off);
                if (NI == 2) pal[l] = *(const uint4*)(Agl + (size_t)l * RPP * K + off);
            }
#pragma unroll
            for (int l = 0; l < NLB; l++)
                pbh[l] = *(const uint4*)(Bg + (size_t)l * RPP * K + off);
        }

        {
            const int jq = lane & 3;
            uint32_t ah[MT][4], al[MT][4], bh[NTT][2];
#pragma unroll
            for (int mt = 0; mt < MT; mt++) {
                int row = wm * WTM + mt * 16 + (lane >> 2);
                ah[mt][0] = As[cur][row][jq];
                ah[mt][1] = As[cur][row + 8][jq];
                ah[mt][2] = As[cur][row][jq + 4];
                ah[mt][3] = As[cur][row + 8][jq + 4];
                if (NI == 2) {
                    al[mt][0] = As[cur][row][jq + 8];
                    al[mt][1] = As[cur][row + 8][jq + 8];
                    al[mt][2] = As[cur][row][jq + 12];
                    al[mt][3] = As[cur][row + 8][jq + 12];
                }
            }
#pragma unroll
            for (int nt = 0; nt < NTT; nt++) {
                int nr = wn * WTN + nt * 8 + (lane >> 2);
                bh[nt][0] = Bs[cur][nr][jq];
                bh[nt][1] = Bs[cur][nr][jq + 4];
            }
#pragma unroll
            for (int mt = 0; mt < MT; mt++)
#pragma unroll
                for (int nt = 0; nt < NTT; nt++) {
                    mma_f16(acc[mt][nt][0], acc[mt][nt][1], acc[mt][nt][2], acc[mt][nt][3],
                            ah[mt][0], ah[mt][1], ah[mt][2], ah[mt][3],
                            bh[nt][0], bh[nt][1]);
                    if (NI == 2)
                        mma_f16(acc[mt][nt][0], acc[mt][nt][1], acc[mt][nt][2], acc[mt][nt][3],
                                al[mt][0], al[mt][1], al[mt][2], al[mt][3],
                                bh[nt][0], bh[nt][1]);
                }
        }

        if (kc + 1 < nk) store_tiles(cur ^ 1);
        __syncthreads();
    }

    // ---------------- epilogue ----------------
    float spsum = 0.f;
#pragma unroll
    for (int mt = 0; mt < MT; mt++) {
        int row = bm + wm * WTM + mt * 16 + (lane >> 2);
#pragma unroll
        for (int nt = 0; nt < NTT; nt++) {
            int col = bn + wn * WTN + nt * 8 + (lane & 3) * 2;
            float* a4 = acc[mt][nt];
            size_t i0 = (size_t)row * N + col;
            size_t i1 = (size_t)(row + 8) * N + col;
            float2 r0 = make_float2(a4[0], a4[1]);
            float2 r1 = make_float2(a4[2], a4[3]);
            if (EPI == 1) {
                float2 o0 = *(const float2*)(C + i0);
                float2 o1 = *(const float2*)(C + i1);
                r0.x += o0.x; r0.y += o0.y;
                r1.x += o1.x; r1.y += o1.y;
            } else if (EPI == 2) {
                r0.x = r0.x / (1.f + expf(-r0.x));
                r0.y = r0.y / (1.f + expf(-r0.y));
                r1.x = r1.x / (1.f + expf(-r1.x));
                r1.y = r1.y / (1.f + expf(-r1.y));
            } else if (EPI == 3) {
                float2 g0 = *(const float2*)(G + i0);
                float2 g1v = *(const float2*)(G + i1);
                r0.x *= g0.x; r0.y *= g0.y;
                r1.x *= g1v.x; r1.y *= g1v.y;
            } else if (EPI == 4) {
                spsum += softplusf(r0.x) + softplusf(r0.y) +
                         softplusf(r1.x) + softplusf(r1.y);
            } else if (EPI == 5) {
                int p = (col & 63) >> 1;
                {
                    float2 cs = g_rope[(row & (S_ - 1)) * 32 + p];
                    float xr = r0.x, xi = r0.y;
                    r0.x = xr * cs.x - xi * cs.y;
                    r0.y = xr * cs.y + xi * cs.x;
                }
                {
                    float2 cs = g_rope[((row + 8) & (S_ - 1)) * 32 + p];
                    float xr = r1.x, xi = r1.y;
                    r1.x = xr * cs.x - xi * cs.y;
                    r1.y = xr * cs.y + xi * cs.x;
                }
            }
            if (EPI == 3) {
                __half2 h0 = __floats2half2_rn(r0.x, r0.y);
                __half2 h1 = __floats2half2_rn(r1.x, r1.y);
                __half2 l0 = __floats2half2_rn(r0.x - __half2float(__low2half(h0)),
                                               r0.y - __half2float(__high2half(h0)));
                __half2 l1 = __floats2half2_rn(r1.x - __half2float(__low2half(h1)),
                                               r1.y - __half2float(__high2half(h1)));
                *(__half2*)(Oh + i0) = h0;
                *(__half2*)(Oh + i1) = h1;
                *(__half2*)(Ol + i0) = l0;
                *(__half2*)(Ol + i1) = l1;
            } else {
                *(float2*)(C + i0) = r0;
                *(float2*)(C + i1) = r1;
            }
        }
    }
    if (EPI == 4) {
        sred[tid] = spsum; __syncthreads();
        for (int st = THREADS / 2; st > 0; st >>= 1) {
            if (tid < st) sred[tid] += sred[tid + st];
            __syncthreads();
        }
        if (tid == 0) atomicAdd(&g_acc[0], (double)sred[0]);
    }
}

template<int BM, int BN, int WM, int WN, int EPI, int NI>
__global__ __launch_bounds__(WM * WN * 32)
void gemm_f16(const __half* __restrict__ Ah, const __half* __restrict__ Al,
              const __half* __restrict__ Bw,
              float* __restrict__ C, const float* __restrict__ G,
              __half* __restrict__ Oh, __half* __restrict__ Ol, int N, int K) {
    gemm_f16_core<BM, BN, WM, WN, EPI, NI>(Ah, Al, Bw, C, G, Oh, Ol, N, K,
                                           blockIdx.x * BM, blockIdx.y * BN);
}

// fused q/k/v (blockIdx.z selects weight/output); q,k get fused RoPE (EPI5)
__global__ __launch_bounds__(128)
void gemm_qkv_f16(const __half* __restrict__ Ah, int layer_off,
                  float* __restrict__ C0, float* __restrict__ C1, float* __restrict__ C2) {
    if (blockIdx.z == 0)
        gemm_f16_core<64, 64, 2, 2, 5, 1>(Ah, nullptr, g_wq + layer_off, C0, nullptr,
                                          nullptr, nullptr, D_, D_,
                                          blockIdx.x * 64, blockIdx.y * 64);
    else if (blockIdx.z == 1)
        gemm_f16_core<64, 64, 2, 2, 5, 1>(Ah, nullptr, g_wk + layer_off, C1, nullptr,
                                          nullptr, nullptr, D_, D_,
                                          blockIdx.x * 64, blockIdx.y * 64);
    else
        gemm_f16_core<64, 64, 2, 2, 0, 1>(Ah, nullptr, g_wv + layer_off, C2, nullptr,
                                          nullptr, nullptr, D_, D_,
                                          blockIdx.x * 64, blockIdx.y * 64);
}

// fused heads: z=0 -> logits (EPI0, w_out); z=1 -> c + softplus (EPI4, w_ctx)
__global__ __launch_bounds__(256)
void gemm_heads_f16(const __half* __restrict__ Ah,
                    float* __restrict__ Cout, float* __restrict__ Cc) {
    if (blockIdx.z == 0)
        gemm_f16_core<128, 128, 2, 4, 0, 1>(Ah, nullptr, g_wout, Cout, nullptr,
                                            nullptr, nullptr, V_, D_,
                                            blockIdx.x * 128, blockIdx.y * 128);
    else
        gemm_f16_core<128, 128, 2, 4, 4, 1>(Ah, nullptr, g_wctx, Cc, nullptr,
                                            nullptr, nullptr, V_, D_,
                                            blockIdx.x * 128, blockIdx.y * 128);
}

// ---------------- flash-style attention (writes o as fp16 hi) ----------------
__global__ __launch_bounds__(256)
void attn_flash() {
    const int qt = blockIdx.x;
    const int bh = blockIdx.y;
    const int b = bh / H_, h = bh - (bh / H_) * H_;
    const int tid = threadIdx.x;
    const int q  = tid >> 2;
    const int dg = (tid & 3) * 16;
    const int q0 = qt * 64;

    __shared__ float KS[64][68];
    __shared__ float Vs[64][68];
    __shared__ float rowm[64], rows[64], cfs[64];

    float4 qr[16];
    const float* qp = g_q + ((size_t)(b * S_ + q0 + q)) * D_ + h * HD_;
#pragma unroll
    for (int j = 0; j < 16; j++) qr[j] = *(const float4*)(qp + 4 * j);

    float acc[16];
#pragma unroll
    for (int j = 0; j < 16; j++) acc[j] = 0.f;
    if (tid < 64) { rowm[tid] = -1e30f; rows[tid] = 0.f; }

    for (int k0 = 0; k0 <= q0; k0 += 64) {
        {
            int r = tid >> 2, c = (tid & 3) * 16;
            const float* kp = g_k + ((size_t)(b * S_ + k0 + r)) * D_ + h * HD_ + c;
            const float* vp = g_v + ((size_t)(b * S_ + k0 + r)) * D_ + h * HD_ + c;
#pragma unroll
            for (int j = 0; j < 4; j++) {
                *(float4*)&KS[r][c + 4 * j] = *(const float4*)(kp + 4 * j);
                *(float4*)&Vs[r][c + 4 * j] = *(const float4*)(vp + 4 * j);
            }
        }
        __syncthreads();

        float sreg[16];
        {
            const int kb = (tid & 3) * 16;
#pragma unroll
            for (int j = 0; j < 16; j++) {
                int kk = kb + j;
                float d = 0.f;
#pragma unroll
                for (int t4 = 0; t4 < 16; t4++) {
                    float4 kv = *(const float4*)&KS[kk][4 * t4];
                    d += qr[t4].x * kv.x + qr[t4].y * kv.y +
                         qr[t4].z * kv.z + qr[t4].w * kv.w;
                }
                sreg[j] = (k0 + kk <= q0 + q) ? d * 0.125f : -1e30f;
            }
        }
        __syncthreads();

        {
            const int kb = (tid & 3) * 16;
#pragma unroll
            for (int j = 0; j < 16; j++) KS[q][kb + j] = sreg[j];
        }
        __syncthreads();

        if (tid < 64) {
            float mo = rowm[tid];
            float tm = mo;
#pragma unroll 8
            for (int kk = 0; kk < 64; kk++) tm = fmaxf(tm, KS[tid][kk]);
            float cf = expf(mo - tm);
            float ps = 0.f;
#pragma unroll 8
            for (int kk = 0; kk < 64; kk++) {
                float p = expf(KS[tid][kk] - tm);
                KS[tid][kk] = p;
                ps += p;
            }
            rowm[tid] = tm;
            rows[tid] = rows[tid] * cf + ps;
            cfs[tid] = cf;
        }
        __syncthreads();

        {
            float cf = cfs[q];
#pragma unroll
            for (int j = 0; j < 16; j++) acc[j] *= cf;
            for (int kk = 0; kk < 64; kk++) {
                float p = KS[q][kk];
#pragma unroll
                for (int j4 = 0; j4 < 4; j4++) {
                    float4 vv = *(const float4*)&Vs[kk][dg + 4 * j4];
                    acc[4 * j4 + 0] += p * vv.x;
                    acc[4 * j4 + 1] += p * vv.y;
                    acc[4 * j4 + 2] += p * vv.z;
                    acc[4 * j4 + 3] += p * vv.w;
                }
            }
        }
        __syncthreads();
    }

    float inv = 1.f / rows[q];
    size_t base = ((size_t)(b * S_ + q0 + q)) * D_ + h * HD_ + dg;
#pragma unroll
    for (int j2 = 0; j2 < 8; j2++) {
        float v0 = acc[2 * j2] * inv, v1 = acc[2 * j2 + 1] * inv;
        *(__half2*)(g_oh + base + 2 * j2) = __floats2half2_rn(v0, v1);
    }
}

// ---------------- sparse BCE correction ----------------
__global__ void corr_kernel(const int* __restrict__ y) {
    int s = blockIdx.x * blockDim.x + threadIdx.x;
    if (s >= S_) return;
    int tok[2][FCS_];
    for (int b = 0; b < 2; b++)
        for (int j = 0; j < FCS_; j++)
            tok[b][j] = y[b * YW_ + (FCS_ - 1) + ((s - (FCS_ - 1) + j + S_) & (S_ - 1))];
    double dsum = 0.0;
    for (int b = 0; b < 2; b++)
        for (int j = 0; j < FCS_; j++) {
            int v = tok[b][j];
            bool first = true;
            for (int b2 = 0; b2 <= b && first; b2++) {
                int jmax = (b2 == b) ? j : FCS_;
                for (int j2 = 0; j2 < jmax; j2++)
                    if (tok[b2][j2] == v) { first = false; break; }
            }
            if (!first) continue;
            int c0 = 0, c1 = 0;
            for (int j2 = 0; j2 < FCS_; j2++) {
                c0 += (tok[0][j2] == v);
                c1 += (tok[1][j2] == v);
            }
            float w = (c0 > 1 || c1 > 1) ? 1.5f : 1.0f;
            for (int b2 = 0; b2 < 2; b2++) {
                float cv = g_c[((size_t)(b2 * S_ + s)) * V_ + v];
                float t  = ((b2 == 0 ? c0 : c1) > 0) ? 1.f : 0.f;
                dsum += (double)((w - 1.f) * softplusf(cv) - w * t * cv);
            }
        }
    atomicAdd(&g_acc[1], dsum);
}

// ---------------- logits += context (ring window) + fused LSE partials ----
// context[s] = sum_{d=1..8} e^(8-d) * c[s-d];  also accumulates
// g_rowsum[row] += sum_v exp(logit_final - 20)  (fixed-max logsumexp)
#define CTX_CHUNK 128
__global__ void ctx_nll_kernel(float* __restrict__ logits, const float* __restrict__ conv_w) {
    int v = blockIdx.x * blockDim.x + threadIdx.x;
    if (v >= V_) return;
    int b  = blockIdx.y;
    int s0 = blockIdx.z * CTX_CHUNK;
    float e = expf(-conv_w[0]);

    float pw[FCS_];
    pw[FCS_ - 1] = 1.f;
#pragma unroll
    for (int d = FCS_ - 1; d >= 1; --d) pw[d - 1] = pw[d] * e;

    float ring[FCS_];
#pragma unroll
    for (int j = 1; j <= FCS_; j++) {
        int sp = s0 - j;
        ring[(8 - j) & 7] = (sp >= 0) ? g_c[((size_t)(b * S_ + sp)) * V_ + v] : 0.f;
    }

    for (int t = 0; t < CTX_CHUNK / 8; t++) {
#pragma unroll
        for (int u = 0; u < 8; u++) {
            int s = s0 + 8 * t + u;
            size_t idx = ((size_t)(b * S_ + s)) * V_ + v;
            float ctx = 0.f;
#pragma unroll
            for (int d = 1; d <= FCS_; d++)
                ctx += pw[d - 1] * ring[(u - d) & 7];
            float lv = logits[idx] + ctx;
            logits[idx] = lv;
            ring[u] = g_c[idx];
            // fused LSE partial (fixed max = 20)
            float we = expf(lv - 20.f);
#pragma unroll
            for (int o = 16; o > 0; o >>= 1)
                we += __shfl_down_sync(0xffffffffu, we, o);
            if ((threadIdx.x & 31) == 0)
                atomicAdd(&g_rowsum[b * S_ + s], we);
        }
    }
}

// ---------------- NLL gather (uses g_rowsum) ----------------
__global__ void nll_fin(const float* __restrict__ logits, const int* __restrict__ y) {
    int row = blockIdx.x * blockDim.x + threadIdx.x;
    if (row >= NT_) return;
    int b = row / S_, s = row - (row / S_) * S_;
    int yt = y[b * YW_ + s];
    if (yt != -1) {
        float lse = 20.f + logf(g_rowsum[row]);
        atomicAdd(&g_acc[2], (double)(lse - logits[(size_t)row * V_ + yt]));
        atomicAdd(&g_acc[3], 1.0);
    }
}

__global__ void finalize_kernel(float* __restrict__ out) {
    double cnt = g_acc[3] < 1.0 ? 1.0 : g_acc[3];
    out[(size_t)NT_ * V_]     = (float)(g_acc[2] / cnt);
    out[(size_t)NT_ * V_ + 1] = (float)((g_acc[0] + g_acc[1]) / ((double)NT_ * (double)V_));
}

// ---------------- launcher ----------------
extern "C" void kernel_launch(void* const* d_in, const int* in_sizes, int n_in,
                              void* d_out, int out_size) {
    const int*   x      = (const int*)  d_in[0];
    const int*   y      = (const int*)  d_in[1];
    const float* emb    = (const float*)d_in[2];
    const float* wq     = (const float*)d_in[3];
    const float* wk     = (const float*)d_in[4];
    const float* wv     = (const float*)d_in[5];
    const float* wo     = (const float*)d_in[6];
    const float* w1     = (const float*)d_in[7];
    const float* w2     = (const float*)d_in[8];
    const float* w3     = (const float*)d_in[9];
    const float* attn_n = (const float*)d_in[10];
    const float* ffn_n  = (const float*)d_in[11];
    const float* out_n  = (const float*)d_in[12];
    const float* w_out  = (const float*)d_in[13];
    const float* w_ctx  = (const float*)d_in[14];
    const float* conv_w = (const float*)d_in[15];
    float* out = (float*)d_out;

    float *h_, *q_, *k_, *v_, *g1_, *c_;
    __half *ah_, *al_, *oh_, *uh_, *ul_;
    __half *wo_f, *w1_f, *w3_f, *w2_f;
    cudaGetSymbolAddress((void**)&h_,  g_h);
    cudaGetSymbolAddress((void**)&q_,  g_q);
    cudaGetSymbolAddress((void**)&k_,  g_k);
    cudaGetSymbolAddress((void**)&v_,  g_v);
    cudaGetSymbolAddress((void**)&g1_, g_g1);
    cudaGetSymbolAddress((void**)&c_,  g_c);
    cudaGetSymbolAddress((void**)&ah_, g_ah);
    cudaGetSymbolAddress((void**)&al_, g_al);
    cudaGetSymbolAddress((void**)&oh_, g_oh);
    cudaGetSymbolAddress((void**)&uh_, g_uh);
    cudaGetSymbolAddress((void**)&ul_, g_ul);
    cudaGetSymbolAddress((void**)&wo_f, g_wo);
    cudaGetSymbolAddress((void**)&w1_f, g_w1);
    cudaGetSymbolAddress((void**)&w3_f, g_w3);
    cudaGetSymbolAddress((void**)&w2_f, g_w2);

    embed_kernel<<<(NT_ * D_ + 255) / 256, 256>>>(x, emb);
    wconv_all<<<2048, 256>>>(wq, wk, wv, wo, w1, w3, w2, w_out, w_ctx);

    dim3 gQKV(NT_ / 64, D_ / 64, 3);     // 16 x 12 x 3 (64x64 tiles)
    dim3 gDs (NT_ / 64, D_ / 64);        // 16 x 12
    dim3 gF  (NT_ / 128, F_ / 64);       // 8 x 32 (128x64 tiles)
    dim3 gHD (NT_ / 128, V_ / 128, 2);   // 8 x 250 x 2 (fused heads)

    for (int i = 0; i < L_; i++) {
        int offDD = i * D_ * D_;
        int offFD = i * F_ * D_;

        // attn path: plain fp16 (1 mma/k16), rope fused into q/k epilogues
        rmsnorm_kernel<1><<<NT_, 256>>>(h_, attn_n + i * D_, ah_, nullptr);
        gemm_qkv_f16<<<gQKV, 128>>>(ah_, offDD, q_, k_, v_);
        attn_flash<<<dim3(S_ / 64, B_ * H_), 256>>>();
        gemm_f16<64, 64, 2, 2, 1, 1><<<gDs, 128>>>(oh_, nullptr, wo_f + offDD,
                                                   h_, nullptr, nullptr, nullptr, D_, D_);

        // ffn path: A-split fp16 (2 mma/k16; only weights round)
        rmsnorm_kernel<2><<<NT_, 256>>>(h_, ffn_n + i * D_, ah_, al_);
        gemm_f16<128, 64, 2, 2, 2, 2><<<gF, 128>>>(ah_, al_, w1_f + offFD,
                                                   g1_, nullptr, nullptr, nullptr, F_, D_);
        gemm_f16<128, 64, 2, 2, 3, 2><<<gF, 128>>>(ah_, al_, w3_f + offFD,
                                                   nullptr, g1_, uh_, ul_, F_, D_);
        gemm_f16<64, 64, 2, 2, 1, 2><<<gDs, 128>>>(uh_, ul_, w2_f + offFD,
                                                   h_, nullptr, nullptr, nullptr, D_, F_);
    }

    // fused heads: plain fp16 (1 mma/k16), one launch, 500 CTAs
    rmsnorm_kernel<1><<<NT_, 256>>>(h_, out_n, ah_, nullptr);
    gemm_heads_f16<<<gHD, 256>>>(ah_, out, c_);

    corr_kernel<<<(S_ + 255) / 256, 256>>>(y);
    ctx_nll_kernel<<<dim3(V_ / 256, B_, S_ / CTX_CHUNK), 256>>>(out, conv_w);
    nll_fin<<<(NT_ + 255) / 256, 256>>>(out, y);
    finalize_kernel<<<1, 1>>>(out);
}

// round 15
// speedup vs baseline: 1.0367x; 1.0367x over previous
#include <cuda_runtime.h>
#include <cuda_fp16.h>
#include <math.h>
#include <stdint.h>

#define B_  2
#define S_  512
#define V_  32000
#define D_  768
#define F_  2048
#define L_  4
#define H_  12
#define HD_ 64
#define FCS_ 8
#define YW_ (S_ + FCS_ - 1)   /* 519 */
#define NT_ (B_ * S_)         /* 1024 rows */

// ---------------- static scratch (allocation-free rule) ----------------
__device__ float  g_h [NT_ * D_];
__device__ float  g_q [NT_ * D_];
__device__ float  g_k [NT_ * D_];
__device__ float  g_v [NT_ * D_];
__device__ float  g_g1[NT_ * F_];
__device__ float  g_c [NT_ * V_];          // context head logits c (131 MB)
__device__ float2 g_rope[S_ * 32];
__device__ double g_acc[4];                // [0]=softplus [1]=delta [2]=nll [3]=valid

// fp16 activations (hi + lo residual where needed)
__device__ __align__(16) __half g_ah[NT_ * D_], g_al[NT_ * D_];
__device__ __align__(16) __half g_oh[NT_ * D_];
__device__ __align__(16) __half g_uh[NT_ * F_], g_ul[NT_ * F_];

// fp16 weights (converted once per launch)
__device__ __align__(16) __half g_wq[L_*D_*D_];
__device__ __align__(16) __half g_wk[L_*D_*D_];
__device__ __align__(16) __half g_wv[L_*D_*D_];
__device__ __align__(16) __half g_wo[L_*D_*D_];
__device__ __align__(16) __half g_w1[L_*F_*D_];
__device__ __align__(16) __half g_w3[L_*F_*D_];
__device__ __align__(16) __half g_w2[L_*D_*F_];
__device__ __align__(16) __half g_wout[V_*D_];
__device__ __align__(16) __half g_wctx[V_*D_];

__device__ __forceinline__ float softplusf(float x) {
    if (x > 15.0f) return x;
    return log1pf(expf(x));
}

__device__ __forceinline__ void mma_f16(float& c0, float& c1, float& c2, float& c3,
                                        uint32_t a0, uint32_t a1, uint32_t a2, uint32_t a3,
                                        uint32_t b0, uint32_t b1) {
    asm volatile("mma.sync.aligned.m16n8k16.row.col.f32.f16.f16.f32 "
                 "{%0,%1,%2,%3}, {%4,%5,%6,%7}, {%8,%9}, {%0,%1,%2,%3};"
                 : "+f"(c0), "+f"(c1), "+f"(c2), "+f"(c3)
                 : "r"(a0), "r"(a1), "r"(a2), "r"(a3), "r"(b0), "r"(b1));
}

__device__ __forceinline__ void ldsm_x4(uint32_t& r0, uint32_t& r1,
                                        uint32_t& r2, uint32_t& r3, uint32_t addr) {
    asm volatile("ldmatrix.sync.aligned.m8n8.x4.shared.b16 {%0,%1,%2,%3}, [%4];"
                 : "=r"(r0), "=r"(r1), "=r"(r2), "=r"(r3) : "r"(addr));
}

// ---------------- weight convert fp32 -> fp16 (MLP=4 grid-stride) ----------------
__global__ void wconv_kernel(const float* __restrict__ src, __half* __restrict__ dst, int n4) {
    const int stride = blockDim.x * gridDim.x;
    int i = blockIdx.x * blockDim.x + threadIdx.x;
    float4 v[4];
    int idx[4];
#pragma unroll
    for (int u = 0; u < 4; u++) {
        idx[u] = i + u * stride;
        if (idx[u] < n4) v[u] = ((const float4*)src)[idx[u]];
    }
#pragma unroll
    for (int u = 0; u < 4; u++) {
        if (idx[u] < n4) {
            ((__half2*)dst)[2 * idx[u]]     = __floats2half2_rn(v[u].x, v[u].y);
            ((__half2*)dst)[2 * idx[u] + 1] = __floats2half2_rn(v[u].z, v[u].w);
        }
    }
}

// ---------------- embedding gather (+ acc zero + rope table fold-in) ----------
__global__ void embed_kernel(const int* __restrict__ x, const float* __restrict__ emb) {
    int i = blockIdx.x * blockDim.x + threadIdx.x;
    if (i < 4) g_acc[i] = 0.0;
    if (i < S_ * 32) {
        int s = i / 32, p = i - (i / 32) * 32;
        float f   = expf((float)(2 * p) * (-logf(10000.0f) / (float)HD_));
        float ang = (float)s * f;
        double a  = (double)ang;
        g_rope[i] = make_float2((float)cos(a), (float)sin(a));
    }
    if (i >= NT_ * D_) return;
    int row = i / D_;
    int d   = i - row * D_;
    g_h[i] = emb[(size_t)x[row] * D_ + d];
}

// ---------------- rmsnorm (SPLIT: 1=fp16 hi only, 2=fp16 hi+lo) ----------------
template<int SPLIT>
__global__ void rmsnorm_kernel(const float* __restrict__ in, const float* __restrict__ w,
                               __half* __restrict__ oh, __half* __restrict__ ol) {
    int row = blockIdx.x;
    const float* ip = in + row * D_;
    __shared__ float red[256];
    float ss = 0.f;
    for (int d = threadIdx.x; d < D_; d += 256) { float v = ip[d]; ss += v * v; }
    red[threadIdx.x] = ss; __syncthreads();
    for (int st = 128; st > 0; st >>= 1) {
        if (threadIdx.x < st) red[threadIdx.x] += red[threadIdx.x + st];
        __syncthreads();
    }
    float rs = rsqrtf(red[0] / (float)D_ + 1e-5f);
    for (int d = threadIdx.x; d < D_; d += 256) {
        float v = ip[d] * rs * w[d];
        __half h = __float2half_rn(v);
        oh[row * D_ + d] = h;
        if (SPLIT == 2) ol[row * D_ + d] = __float2half_rn(v - __half2float(h));
    }
}

#define TLD 20   /* smem row stride (u32): conflict-free for ldmatrix (8 rows x 16B) */

// =======================================================================
//  fp16 NT-GEMM:  C[m,n] (op)= sum_k A[m,k]*W[n,k]
//  Fragments via ldmatrix.x4 (A and B; mapping == validated scalar pattern).
//  NI=1: A=hi only (1 mma/k16).  NI=2: A=hi+lo residual (2 mma/k16).
//  EPI: 0=store 1=add 2=silu 3=mulG->fp16 hi/lo 4=store+softplus 5=rope-store
// =======================================================================
template<int BM, int BN, int WM, int WN, int EPI, int NI>
__device__ __forceinline__ void gemm_f16_core(const __half* __restrict__ Ah,
                                              const __half* __restrict__ Al,
                                              const __half* __restrict__ Bw,
                                              float* __restrict__ C,
                                              const float* __restrict__ G,
                                              __half* __restrict__ Oh,
                                              __half* __restrict__ Ol,
                                              int N, int K, int bm, int bn) {
    constexpr int THREADS = WM * WN * 32;
    constexpr int WTM = BM / WM;
    constexpr int WTN = BN / WN;
    constexpr int MT  = WTM / 16;
    constexpr int NTT = WTN / 8;
    constexpr int RPP = THREADS / 2;
    constexpr int NLA = BM / RPP;
    constexpr int NLB = BN / RPP;

    __shared__ __align__(16) uint32_t As[2][BM][TLD];
    __shared__ __align__(16) uint32_t Bs[2][BN][TLD];
    __shared__ float sred[THREADS];

    const int tid  = threadIdx.x;
    const int lane = tid & 31;
    const int wid  = tid >> 5;
    const int wm   = wid / WN;
    const int wn   = wid % WN;

    const int lr = tid >> 1;
    const int ks = (tid & 1) * 8;   // element offset 0/8 in k16 chunk
    const int js = ks >> 1;         // u32 pair offset 0/4
    const __half* Agh = Ah + (size_t)(bm + lr) * K + ks;
    const __half* Agl = (NI == 2) ? Al + (size_t)(bm + lr) * K + ks : nullptr;
    const __half* Bg  = Bw + (size_t)(bn + lr) * K + ks;

    float acc[MT][NTT][4];
#pragma unroll
    for (int i = 0; i < MT; i++)
#pragma unroll
        for (int j = 0; j < NTT; j++)
#pragma unroll
            for (int q = 0; q < 4; q++) acc[i][j][q] = 0.f;

    uint4 pah[NLA], pal[NLA], pbh[NLB];

#pragma unroll
    for (int l = 0; l < NLA; l++) {
        pah[l] = *(const uint4*)(Agh + (size_t)l * RPP * K);
        if (NI == 2) pal[l] = *(const uint4*)(Agl + (size_t)l * RPP * K);
    }
#pragma unroll
    for (int l = 0; l < NLB; l++)
        pbh[l] = *(const uint4*)(Bg + (size_t)l * RPP * K);

    auto store_tiles = [&](int buf) {
#pragma unroll
        for (int l = 0; l < NLA; l++) {
            *(uint4*)&As[buf][lr + l * RPP][js] = pah[l];
            if (NI == 2) *(uint4*)&As[buf][lr + l * RPP][8 + js] = pal[l];
        }
#pragma unroll
        for (int l = 0; l < NLB; l++)
            *(uint4*)&Bs[buf][lr + l * RPP][js] = pbh[l];
    };

    store_tiles(0);
    __syncthreads();

    // ldmatrix per-thread base addresses (thread t -> row base of its 8x8 matrix)
    const int lg8 = lane & 7;            // row within 8x8
    const int selA = (lane >> 3) & 1;    // A: row-half (0/8);  B: k-col (0/4)
    const int selB = lane >> 4;          // A: k-col (0/4);     B: n-subtile (0/8)
    const uint32_t aBase =
        (uint32_t)__cvta_generic_to_shared(&As[0][wm * WTM + selA * 8 + lg8][selB * 4]);
    const uint32_t bBase =
        (uint32_t)__cvta_generic_to_shared(&Bs[0][wn * WTN + selB * 8 + lg8][selA * 4]);
    constexpr uint32_t ABUF  = BM * TLD * 4;
    constexpr uint32_t BBUF  = BN * TLD * 4;
    constexpr uint32_t T16   = 16 * TLD * 4;   // 16 rows in bytes

    const int nk = K / 16;
    for (int kc = 0; kc < nk; kc++) {
        const int cur = kc & 1;
        if (kc + 1 < nk) {
            const int off = (kc + 1) * 16;
#pragma unroll
            for (int l = 0; l < NLA; l++) {
                pah[l] = *(const uint4*)(Agh + (size_t)l * RPP * K + off);
                if (NI == 2) pal[l] = *(const uint4*)(Agl + (size_t)l * RPP * K + off);
            }
#pragma unroll
            for (int l = 0; l < NLB; l++)
                pbh[l] = *(const uint4*)(Bg + (size_t)l * RPP * K + off);
        }

        {
            const uint32_t aOff = aBase + (uint32_t)cur * ABUF;
            const uint32_t bOff = bBase + (uint32_t)cur * BBUF;
            uint32_t ah[MT][4], al[MT][4], bh[NTT][2];
#pragma unroll
            for (int mt = 0; mt < MT; mt++) {
                ldsm_x4(ah[mt][0], ah[mt][1], ah[mt][2], ah[mt][3], aOff + mt * T16);
                if (NI == 2)
                    ldsm_x4(al[mt][0], al[mt][1], al[mt][2], al[mt][3],
                            aOff + mt * T16 + 8 * 4);
            }
#pragma unroll
            for (int p = 0; p < NTT / 2; p++)
                ldsm_x4(bh[2*p][0], bh[2*p][1], bh[2*p+1][0], bh[2*p+1][1],
                        bOff + p * T16);
#pragma unroll
            for (int mt = 0; mt < MT; mt++)
#pragma unroll
                for (int nt = 0; nt < NTT; nt++) {
                    mma_f16(acc[mt][nt][0], acc[mt][nt][1], acc[mt][nt][2], acc[mt][nt][3],
                            ah[mt][0], ah[mt][1], ah[mt][2], ah[mt][3],
                            bh[nt][0], bh[nt][1]);
                    if (NI == 2)
                        mma_f16(acc[mt][nt][0], acc[mt][nt][1], acc[mt][nt][2], acc[mt][nt][3],
                                al[mt][0], al[mt][1], al[mt][2], al[mt][3],
                                bh[nt][0], bh[nt][1]);
                }
        }

        if (kc + 1 < nk) store_tiles(cur ^ 1);
        __syncthreads();
    }

    // ---------------- epilogue ----------------
    float spsum = 0.f;
#pragma unroll
    for (int mt = 0; mt < MT; mt++) {
        int row = bm + wm * WTM + mt * 16 + (lane >> 2);
#pragma unroll
        for (int nt = 0; nt < NTT; nt++) {
            int col = bn + wn * WTN + nt * 8 + (lane & 3) * 2;
            float* a4 = acc[mt][nt];
            size_t i0 = (size_t)row * N + col;
            size_t i1 = (size_t)(row + 8) * N + col;
            float2 r0 = make_float2(a4[0], a4[1]);
            float2 r1 = make_float2(a4[2], a4[3]);
            if (EPI == 1) {
                float2 o0 = *(const float2*)(C + i0);
                float2 o1 = *(const float2*)(C + i1);
                r0.x += o0.x; r0.y += o0.y;
                r1.x += o1.x; r1.y += o1.y;
            } else if (EPI == 2) {
                r0.x = r0.x / (1.f + expf(-r0.x));
                r0.y = r0.y / (1.f + expf(-r0.y));
                r1.x = r1.x / (1.f + expf(-r1.x));
                r1.y = r1.y / (1.f + expf(-r1.y));
            } else if (EPI == 3) {
                float2 g0 = *(const float2*)(G + i0);
                float2 g1v = *(const float2*)(G + i1);
                r0.x *= g0.x; r0.y *= g0.y;
                r1.x *= g1v.x; r1.y *= g1v.y;
            } else if (EPI == 4) {
                spsum += softplusf(r0.x) + softplusf(r0.y) +
                         softplusf(r1.x) + softplusf(r1.y);
            } else if (EPI == 5) {
                int p = (col & 63) >> 1;
                {
                    float2 cs = g_rope[(row & (S_ - 1)) * 32 + p];
                    float xr = r0.x, xi = r0.y;
                    r0.x = xr * cs.x - xi * cs.y;
                    r0.y = xr * cs.y + xi * cs.x;
                }
                {
                    float2 cs = g_rope[((row + 8) & (S_ - 1)) * 32 + p];
                    float xr = r1.x, xi = r1.y;
                    r1.x = xr * cs.x - xi * cs.y;
                    r1.y = xr * cs.y + xi * cs.x;
                }
            }
            if (EPI == 3) {
                __half2 h0 = __floats2half2_rn(r0.x, r0.y);
                __half2 h1 = __floats2half2_rn(r1.x, r1.y);
                __half2 l0 = __floats2half2_rn(r0.x - __half2float(__low2half(h0)),
                                               r0.y - __half2float(__high2half(h0)));
                __half2 l1 = __floats2half2_rn(r1.x - __half2float(__low2half(h1)),
                                               r1.y - __half2float(__high2half(h1)));
                *(__half2*)(Oh + i0) = h0;
                *(__half2*)(Oh + i1) = h1;
                *(__half2*)(Ol + i0) = l0;
                *(__half2*)(Ol + i1) = l1;
            } else {
                *(float2*)(C + i0) = r0;
                *(float2*)(C + i1) = r1;
            }
        }
    }
    if (EPI == 4) {
        sred[tid] = spsum; __syncthreads();
        for (int st = THREADS / 2; st > 0; st >>= 1) {
            if (tid < st) sred[tid] += sred[tid + st];
            __syncthreads();
        }
        if (tid == 0) atomicAdd(&g_acc[0], (double)sred[0]);
    }
}

template<int BM, int BN, int WM, int WN, int EPI, int NI>
__global__ __launch_bounds__(WM * WN * 32)
void gemm_f16(const __half* __restrict__ Ah, const __half* __restrict__ Al,
              const __half* __restrict__ Bw,
              float* __restrict__ C, const float* __restrict__ G,
              __half* __restrict__ Oh, __half* __restrict__ Ol, int N, int K) {
    gemm_f16_core<BM, BN, WM, WN, EPI, NI>(Ah, Al, Bw, C, G, Oh, Ol, N, K,
                                           blockIdx.x * BM, blockIdx.y * BN);
}

// fused q/k/v (blockIdx.z selects weight/output); q,k get fused RoPE (EPI5)
__global__ __launch_bounds__(128)
void gemm_qkv_f16(const __half* __restrict__ Ah, int layer_off,
                  float* __restrict__ C0, float* __restrict__ C1, float* __restrict__ C2) {
    if (blockIdx.z == 0)
        gemm_f16_core<64, 64, 2, 2, 5, 1>(Ah, nullptr, g_wq + layer_off, C0, nullptr,
                                          nullptr, nullptr, D_, D_,
                                          blockIdx.x * 64, blockIdx.y * 64);
    else if (blockIdx.z == 1)
        gemm_f16_core<64, 64, 2, 2, 5, 1>(Ah, nullptr, g_wk + layer_off, C1, nullptr,
                                          nullptr, nullptr, D_, D_,
                                          blockIdx.x * 64, blockIdx.y * 64);
    else
        gemm_f16_core<64, 64, 2, 2, 0, 1>(Ah, nullptr, g_wv + layer_off, C2, nullptr,
                                          nullptr, nullptr, D_, D_,
                                          blockIdx.x * 64, blockIdx.y * 64);
}

// fused heads: z=0 -> logits (EPI0, w_out); z=1 -> c + softplus (EPI4, w_ctx)
__global__ __launch_bounds__(256)
void gemm_heads_f16(const __half* __restrict__ Ah,
                    float* __restrict__ Cout, float* __restrict__ Cc) {
    if (blockIdx.z == 0)
        gemm_f16_core<128, 128, 2, 4, 0, 1>(Ah, nullptr, g_wout, Cout, nullptr,
                                            nullptr, nullptr, V_, D_,
                                            blockIdx.x * 128, blockIdx.y * 128);
    else
        gemm_f16_core<128, 128, 2, 4, 4, 1>(Ah, nullptr, g_wctx, Cc, nullptr,
                                            nullptr, nullptr, V_, D_,
                                            blockIdx.x * 128, blockIdx.y * 128);
}

// ---------------- flash-style attention (writes o as fp16 hi) ----------------
__global__ __launch_bounds__(256)
void attn_flash() {
    const int qt = blockIdx.x;
    const int bh = blockIdx.y;
    const int b = bh / H_, h = bh - (bh / H_) * H_;
    const int tid = threadIdx.x;
    const int q  = tid >> 2;
    const int dg = (tid & 3) * 16;
    const int q0 = qt * 64;

    __shared__ float KS[64][68];
    __shared__ float Vs[64][68];
    __shared__ float rowm[64], rows[64], cfs[64];

    float4 qr[16];
    const float* qp = g_q + ((size_t)(b * S_ + q0 + q)) * D_ + h * HD_;
#pragma unroll
    for (int j = 0; j < 16; j++) qr[j] = *(const float4*)(qp + 4 * j);

    float acc[16];
#pragma unroll
    for (int j = 0; j < 16; j++) acc[j] = 0.f;
    if (tid < 64) { rowm[tid] = -1e30f; rows[tid] = 0.f; }

    for (int k0 = 0; k0 <= q0; k0 += 64) {
        {
            int r = tid >> 2, c = (tid & 3) * 16;
            const float* kp = g_k + ((size_t)(b * S_ + k0 + r)) * D_ + h * HD_ + c;
            const float* vp = g_v + ((size_t)(b * S_ + k0 + r)) * D_ + h * HD_ + c;
#pragma unroll
            for (int j = 0; j < 4; j++) {
                *(float4*)&KS[r][c + 4 * j] = *(const float4*)(kp + 4 * j);
                *(float4*)&Vs[r][c + 4 * j] = *(const float4*)(vp + 4 * j);
            }
        }
        __syncthreads();

        float sreg[16];
        {
            const int kb = (tid & 3) * 16;
#pragma unroll
            for (int j = 0; j < 16; j++) {
                int kk = kb + j;
                float d = 0.f;
#pragma unroll
                for (int t4 = 0; t4 < 16; t4++) {
                    float4 kv = *(const float4*)&KS[kk][4 * t4];
                    d += qr[t4].x * kv.x + qr[t4].y * kv.y +
                         qr[t4].z * kv.z + qr[t4].w * kv.w;
                }
                sreg[j] = (k0 + kk <= q0 + q) ? d * 0.125f : -1e30f;
            }
        }
        __syncthreads();

        {
            const int kb = (tid & 3) * 16;
#pragma unroll
            for (int j = 0; j < 16; j++) KS[q][kb + j] = sreg[j];
        }
        __syncthreads();

        if (tid < 64) {
            float mo = rowm[tid];
            float tm = mo;
#pragma unroll 8
            for (int kk = 0; kk < 64; kk++) tm = fmaxf(tm, KS[tid][kk]);
            float cf = expf(mo - tm);
            float ps = 0.f;
#pragma unroll 8
            for (int kk = 0; kk < 64; kk++) {
                float p = expf(KS[tid][kk] - tm);
                KS[tid][kk] = p;
                ps += p;
            }
            rowm[tid] = tm;
            rows[tid] = rows[tid] * cf + ps;
            cfs[tid] = cf;
        }
        __syncthreads();

        {
            float cf = cfs[q];
#pragma unroll
            for (int j = 0; j < 16; j++) acc[j] *= cf;
            for (int kk = 0; kk < 64; kk++) {
                float p = KS[q][kk];
#pragma unroll
                for (int j4 = 0; j4 < 4; j4++) {
                    float4 vv = *(const float4*)&Vs[kk][dg + 4 * j4];
                    acc[4 * j4 + 0] += p * vv.x;
                    acc[4 * j4 + 1] += p * vv.y;
                    acc[4 * j4 + 2] += p * vv.z;
                    acc[4 * j4 + 3] += p * vv.w;
                }
            }
        }
        __syncthreads();
    }

    float inv = 1.f / rows[q];
    size_t base = ((size_t)(b * S_ + q0 + q)) * D_ + h * HD_ + dg;
#pragma unroll
    for (int j2 = 0; j2 < 8; j2++) {
        float v0 = acc[2 * j2] * inv, v1 = acc[2 * j2 + 1] * inv;
        *(__half2*)(g_oh + base + 2 * j2) = __floats2half2_rn(v0, v1);
    }
}

// ---------------- sparse BCE correction ----------------
__global__ void corr_kernel(const int* __restrict__ y) {
    int s = blockIdx.x * blockDim.x + threadIdx.x;
    if (s >= S_) return;
    int tok[2][FCS_];
    for (int b = 0; b < 2; b++)
        for (int j = 0; j < FCS_; j++)
            tok[b][j] = y[b * YW_ + (FCS_ - 1) + ((s - (FCS_ - 1) + j + S_) & (S_ - 1))];
    double dsum = 0.0;
    for (int b = 0; b < 2; b++)
        for (int j = 0; j < FCS_; j++) {
            int v = tok[b][j];
            bool first = true;
            for (int b2 = 0; b2 <= b && first; b2++) {
                int jmax = (b2 == b) ? j : FCS_;
                for (int j2 = 0; j2 < jmax; j2++)
                    if (tok[b2][j2] == v) { first = false; break; }
            }
            if (!first) continue;
            int c0 = 0, c1 = 0;
            for (int j2 = 0; j2 < FCS_; j2++) {
                c0 += (tok[0][j2] == v);
                c1 += (tok[1][j2] == v);
            }
            float w = (c0 > 1 || c1 > 1) ? 1.5f : 1.0f;
            for (int b2 = 0; b2 < 2; b2++) {
                float cv = g_c[((size_t)(b2 * S_ + s)) * V_ + v];
                float t  = ((b2 == 0 ? c0 : c1) > 0) ? 1.f : 0.f;
                dsum += (double)((w - 1.f) * softplusf(cv) - w * t * cv);
            }
        }
    atomicAdd(&g_acc[1], dsum);
}

// ---------------- logits += exp-kernel context (ring-buffer window) ----
#define CTX_CHUNK 128
__global__ void ctx_scan_kernel(float* __restrict__ logits, const float* __restrict__ conv_w) {
    int v = blockIdx.x * blockDim.x + threadIdx.x;
    if (v >= V_) return;
    int b  = blockIdx.y;
    int s0 = blockIdx.z * CTX_CHUNK;
    float e = expf(-conv_w[0]);

    float pw[FCS_];
    pw[FCS_ - 1] = 1.f;
#pragma unroll
    for (int d = FCS_ - 1; d >= 1; --d) pw[d - 1] = pw[d] * e;

    float ring[FCS_];
#pragma unroll
    for (int j = 1; j <= FCS_; j++) {
        int sp = s0 - j;
        ring[(8 - j) & 7] = (sp >= 0) ? g_c[((size_t)(b * S_ + sp)) * V_ + v] : 0.f;
    }

    for (int t = 0; t < CTX_CHUNK / 8; t++) {
#pragma unroll
        for (int u = 0; u < 8; u++) {
            int s = s0 + 8 * t + u;
            size_t idx = ((size_t)(b * S_ + s)) * V_ + v;
            float ctx = 0.f;
#pragma unroll
            for (int d = 1; d <= FCS_; d++)
                ctx += pw[d - 1] * ring[(u - d) & 7];
            logits[idx] += ctx;
            ring[u] = g_c[idx];
        }
    }
}

// ---------------- NLL (one-pass online logsumexp) ----------------
__global__ void nll_kernel(const float* __restrict__ logits, const int* __restrict__ y) {
    int row = blockIdx.x;
    int b = row / S_, s = row - (row / S_) * S_;
    const float* lp = logits + (size_t)row * V_;
    __shared__ float rm[256], rs[256];
    float m = -1e30f, ssum = 0.f;
    for (int v = threadIdx.x; v < V_; v += 256) {
        float xv = lp[v];
        if (xv > m) { ssum = ssum * expf(m - xv) + 1.f; m = xv; }
        else        { ssum += expf(xv - m); }
    }
    rm[threadIdx.x] = m; rs[threadIdx.x] = ssum; __syncthreads();
    for (int st = 128; st > 0; st >>= 1) {
        if (threadIdx.x < st) {
            float m2 = rm[threadIdx.x + st], s2 = rs[threadIdx.x + st];
            float mm = fmaxf(rm[threadIdx.x], m2);
            rs[threadIdx.x] = rs[threadIdx.x] * expf(rm[threadIdx.x] - mm) +
                              s2 * expf(m2 - mm);
            rm[threadIdx.x] = mm;
        }
        __syncthreads();
    }
    if (threadIdx.x == 0) {
        int yt = y[b * YW_ + s];
        if (yt != -1) {
            float lse = rm[0] + logf(rs[0]);
            atomicAdd(&g_acc[2], (double)(lse - lp[yt]));
            atomicAdd(&g_acc[3], 1.0);
        }
    }
}

__global__ void finalize_kernel(float* __restrict__ out) {
    double cnt = g_acc[3] < 1.0 ? 1.0 : g_acc[3];
    out[(size_t)NT_ * V_]     = (float)(g_acc[2] / cnt);
    out[(size_t)NT_ * V_ + 1] = (float)((g_acc[0] + g_acc[1]) / ((double)NT_ * (double)V_));
}

// ---------------- launcher ----------------
extern "C" void kernel_launch(void* const* d_in, const int* in_sizes, int n_in,
                              void* d_out, int out_size) {
    const int*   x      = (const int*)  d_in[0];
    const int*   y      = (const int*)  d_in[1];
    const float* emb    = (const float*)d_in[2];
    const float* wq     = (const float*)d_in[3];
    const float* wk     = (const float*)d_in[4];
    const float* wv     = (const float*)d_in[5];
    const float* wo     = (const float*)d_in[6];
    const float* w1     = (const float*)d_in[7];
    const float* w2     = (const float*)d_in[8];
    const float* w3     = (const float*)d_in[9];
    const float* attn_n = (const float*)d_in[10];
    const float* ffn_n  = (const float*)d_in[11];
    const float* out_n  = (const float*)d_in[12];
    const float* w_out  = (const float*)d_in[13];
    const float* w_ctx  = (const float*)d_in[14];
    const float* conv_w = (const float*)d_in[15];
    float* out = (float*)d_out;

    float *h_, *q_, *k_, *v_, *g1_, *c_;
    __half *ah_, *al_, *oh_, *uh_, *ul_;
    __half *wq_f, *wk_f, *wv_f, *wo_f, *w1_f, *w3_f, *w2_f, *wout_f, *wctx_f;
    cudaGetSymbolAddress((void**)&h_,  g_h);
    cudaGetSymbolAddress((void**)&q_,  g_q);
    cudaGetSymbolAddress((void**)&k_,  g_k);
    cudaGetSymbolAddress((void**)&v_,  g_v);
    cudaGetSymbolAddress((void**)&g1_, g_g1);
    cudaGetSymbolAddress((void**)&c_,  g_c);
    cudaGetSymbolAddress((void**)&ah_, g_ah);
    cudaGetSymbolAddress((void**)&al_, g_al);
    cudaGetSymbolAddress((void**)&oh_, g_oh);
    cudaGetSymbolAddress((void**)&uh_, g_uh);
    cudaGetSymbolAddress((void**)&ul_, g_ul);
    cudaGetSymbolAddress((void**)&wq_f, g_wq);
    cudaGetSymbolAddress((void**)&wk_f, g_wk);
    cudaGetSymbolAddress((void**)&wv_f, g_wv);
    cudaGetSymbolAddress((void**)&wo_f, g_wo);
    cudaGetSymbolAddress((void**)&w1_f, g_w1);
    cudaGetSymbolAddress((void**)&w3_f, g_w3);
    cudaGetSymbolAddress((void**)&w2_f, g_w2);
    cudaGetSymbolAddress((void**)&wout_f, g_wout);
    cudaGetSymbolAddress((void**)&wctx_f, g_wctx);

    embed_kernel<<<(NT_ * D_ + 255) / 256, 256>>>(x, emb);

    // weight converts (fp32 -> fp16, MLP=4)
    {
        int nDD4 = L_ * D_ * D_ / 4;
        int nFD4 = L_ * F_ * D_ / 4;
        int nVD4 = V_ * D_ / 4;
        int gDD = (nDD4 + 1023) / 1024, gFD = (nFD4 + 1023) / 1024, gVD = (nVD4 + 1023) / 1024;
        wconv_kernel<<<gDD, 256>>>(wq, wq_f, nDD4);
        wconv_kernel<<<gDD, 256>>>(wk, wk_f, nDD4);
        wconv_kernel<<<gDD, 256>>>(wv, wv_f, nDD4);
        wconv_kernel<<<gDD, 256>>>(wo, wo_f, nDD4);
        wconv_kernel<<<gFD, 256>>>(w1, w1_f, nFD4);
        wconv_kernel<<<gFD, 256>>>(w3, w3_f, nFD4);
        wconv_kernel<<<gFD, 256>>>(w2, w2_f, nFD4);
        wconv_kernel<<<gVD, 256>>>(w_out, wout_f, nVD4);
        wconv_kernel<<<gVD, 256>>>(w_ctx, wctx_f, nVD4);
    }

    dim3 gQKV(NT_ / 64, D_ / 64, 3);     // 16 x 12 x 3 (64x64 tiles)
    dim3 gDs (NT_ / 64, D_ / 64);        // 16 x 12
    dim3 gF  (NT_ / 128, F_ / 64);       // 8 x 32 (128x64 tiles)
    dim3 gHD (NT_ / 128, V_ / 128, 2);   // 8 x 250 x 2 (fused heads)

    for (int i = 0; i < L_; i++) {
        int offDD = i * D_ * D_;
        int offFD = i * F_ * D_;

        // attn path: plain fp16 (1 mma/k16), rope fused into q/k epilogues
        rmsnorm_kernel<1><<<NT_, 256>>>(h_, attn_n + i * D_, ah_, nullptr);
        gemm_qkv_f16<<<gQKV, 128>>>(ah_, offDD, q_, k_, v_);
        attn_flash<<<dim3(S_ / 64, B_ * H_), 256>>>();
        gemm_f16<64, 64, 2, 2, 1, 1><<<gDs, 128>>>(oh_, nullptr, wo_f + offDD,
                                                   h_, nullptr, nullptr, nullptr, D_, D_);

        // ffn path: A-split fp16 (2 mma/k16; only weights round)
        rmsnorm_kernel<2><<<NT_, 256>>>(h_, ffn_n + i * D_, ah_, al_);
        gemm_f16<128, 64, 2, 2, 2, 2><<<gF, 128>>>(ah_, al_, w1_f + offFD,
                                                   g1_, nullptr, nullptr, nullptr, F_, D_);
        gemm_f16<128, 64, 2, 2, 3, 2><<<gF, 128>>>(ah_, al_, w3_f + offFD,
                                                   nullptr, g1_, uh_, ul_, F_, D_);
        gemm_f16<64, 64, 2, 2, 1, 2><<<gDs, 128>>>(uh_, ul_, w2_f + offFD,
                                                   h_, nullptr, nullptr, nullptr, D_, F_);
    }

    // fused heads: plain fp16 (1 mma/k16), one launch, 500 CTAs
    rmsnorm_kernel<1><<<NT_, 256>>>(h_, out_n, ah_, nullptr);
    gemm_heads_f16<<<gHD, 256>>>(ah_, out, c_);

    corr_kernel<<<(S_ + 255) / 256, 256>>>(y);
    ctx_scan_kernel<<<dim3((V_ + 255) / 256, B_, S_ / CTX_CHUNK), 256>>>(out, conv_w);
    nll_kernel<<<NT_, 256>>>(out, y);
    finalize_kernel<<<1, 1>>>(out);
}

// round 16
// speedup vs baseline: 1.0506x; 1.0135x over previous
#include <cuda_runtime.h>
#include <cuda_fp16.h>
#include <math.h>
#include <stdint.h>

#define B_  2
#define S_  512
#define V_  32000
#define D_  768
#define F_  2048
#define L_  4
#define H_  12
#define HD_ 64
#define FCS_ 8
#define YW_ (S_ + FCS_ - 1)   /* 519 */
#define NT_ (B_ * S_)         /* 1024 rows */

// ---------------- static scratch (allocation-free rule) ----------------
__device__ float  g_h [NT_ * D_];
__device__ float  g_q [NT_ * D_];
__device__ float  g_k [NT_ * D_];
__device__ float  g_v [NT_ * D_];
__device__ float  g_g1[NT_ * F_];
__device__ float  g_c [NT_ * V_];          // context head logits c (131 MB)
__device__ float2 g_rope[S_ * 32];
__device__ double g_acc[4];                // [0]=softplus [1]=delta [2]=nll [3]=valid

// fp16 activations (hi + lo residual where needed)
__device__ __align__(16) __half g_ah[NT_ * D_], g_al[NT_ * D_];
__device__ __align__(16) __half g_oh[NT_ * D_];
__device__ __align__(16) __half g_uh[NT_ * F_], g_ul[NT_ * F_];

// fp16 weights (converted once per launch)
__device__ __align__(16) __half g_wq[L_*D_*D_];
__device__ __align__(16) __half g_wk[L_*D_*D_];
__device__ __align__(16) __half g_wv[L_*D_*D_];
__device__ __align__(16) __half g_wo[L_*D_*D_];
__device__ __align__(16) __half g_w1[L_*F_*D_];
__device__ __align__(16) __half g_w3[L_*F_*D_];
__device__ __align__(16) __half g_w2[L_*D_*F_];
__device__ __align__(16) __half g_wout[V_*D_];
__device__ __align__(16) __half g_wctx[V_*D_];

__device__ __forceinline__ float softplusf(float x) {
    if (x > 15.0f) return x;
    return log1pf(expf(x));
}

__device__ __forceinline__ void mma_f16(float& c0, float& c1, float& c2, float& c3,
                                        uint32_t a0, uint32_t a1, uint32_t a2, uint32_t a3,
                                        uint32_t b0, uint32_t b1) {
    asm volatile("mma.sync.aligned.m16n8k16.row.col.f32.f16.f16.f32 "
                 "{%0,%1,%2,%3}, {%4,%5,%6,%7}, {%8,%9}, {%0,%1,%2,%3};"
                 : "+f"(c0), "+f"(c1), "+f"(c2), "+f"(c3)
                 : "r"(a0), "r"(a1), "r"(a2), "r"(a3), "r"(b0), "r"(b1));
}

__device__ __forceinline__ void ldsm_x4(uint32_t& r0, uint32_t& r1,
                                        uint32_t& r2, uint32_t& r3, uint32_t addr) {
    asm volatile("ldmatrix.sync.aligned.m8n8.x4.shared.b16 {%0,%1,%2,%3}, [%4];"
                 : "=r"(r0), "=r"(r1), "=r"(r2), "=r"(r3) : "r"(addr));
}

// ---------------- weight convert fp32 -> fp16 (MLP=4 grid-stride) ----------------
__global__ void wconv_kernel(const float* __restrict__ src, __half* __restrict__ dst, int n4) {
    const int stride = blockDim.x * gridDim.x;
    int i = blockIdx.x * blockDim.x + threadIdx.x;
    float4 v[4];
    int idx[4];
#pragma unroll
    for (int u = 0; u < 4; u++) {
        idx[u] = i + u * stride;
        if (idx[u] < n4) v[u] = ((const float4*)src)[idx[u]];
    }
#pragma unroll
    for (int u = 0; u < 4; u++) {
        if (idx[u] < n4) {
            ((__half2*)dst)[2 * idx[u]]     = __floats2half2_rn(v[u].x, v[u].y);
            ((__half2*)dst)[2 * idx[u] + 1] = __floats2half2_rn(v[u].z, v[u].w);
        }
    }
}

// ---------------- embedding gather (+ acc zero + rope table fold-in) ----------
__global__ void embed_kernel(const int* __restrict__ x, const float* __restrict__ emb) {
    int i = blockIdx.x * blockDim.x + threadIdx.x;
    if (i < 4) g_acc[i] = 0.0;
    if (i < S_ * 32) {
        int s = i / 32, p = i - (i / 32) * 32;
        float f   = expf((float)(2 * p) * (-logf(10000.0f) / (float)HD_));
        float ang = (float)s * f;
        double a  = (double)ang;
        g_rope[i] = make_float2((float)cos(a), (float)sin(a));
    }
    if (i >= NT_ * D_) return;
    int row = i / D_;
    int d   = i - row * D_;
    g_h[i] = emb[(size_t)x[row] * D_ + d];
}

// ---------------- rmsnorm (SPLIT: 1=fp16 hi only, 2=fp16 hi+lo) ----------------
template<int SPLIT>
__global__ void rmsnorm_kernel(const float* __restrict__ in, const float* __restrict__ w,
                               __half* __restrict__ oh, __half* __restrict__ ol) {
    int row = blockIdx.x;
    const float* ip = in + row * D_;
    __shared__ float red[256];
    float ss = 0.f;
    for (int d = threadIdx.x; d < D_; d += 256) { float v = ip[d]; ss += v * v; }
    red[threadIdx.x] = ss; __syncthreads();
    for (int st = 128; st > 0; st >>= 1) {
        if (threadIdx.x < st) red[threadIdx.x] += red[threadIdx.x + st];
        __syncthreads();
    }
    float rs = rsqrtf(red[0] / (float)D_ + 1e-5f);
    for (int d = threadIdx.x; d < D_; d += 256) {
        float v = ip[d] * rs * w[d];
        __half h = __float2half_rn(v);
        oh[row * D_ + d] = h;
        if (SPLIT == 2) ol[row * D_ + d] = __float2half_rn(v - __half2float(h));
    }
}

#define TLD 20   /* smem row stride (u32): conflict-free for ldmatrix (8 rows x 16B) */

// =======================================================================
//  fp16 NT-GEMM:  C[m,n] (op)= sum_k A[m,k]*W[n,k]
//  MODE 0: KT16, A=hi (1 mma/k16)
//  MODE 1: KT16, A=hi+lo residual (2 mma/k16, same k)      [FFN]
//  MODE 2: KT32, two k16 sub-chunks per buffer (2 mma/chunk, k0 then k1)
//          -- bitwise-identical accumulation order to MODE 0.
//  EPI: 0=store 1=add 2=silu 3=mulG->fp16 hi/lo 4=store+softplus 5=rope-store
// =======================================================================
template<int BM, int BN, int WM, int WN, int EPI, int MODE>
__device__ __forceinline__ void gemm_f16_core(const __half* __restrict__ Ah,
                                              const __half* __restrict__ Al,
                                              const __half* __restrict__ Bw,
                                              float* __restrict__ C,
                                              const float* __restrict__ G,
                                              __half* __restrict__ Oh,
                                              __half* __restrict__ Ol,
                                              int N, int K, int bm, int bn) {
    constexpr int THREADS = WM * WN * 32;
    constexpr int WTM = BM / WM;
    constexpr int WTN = BN / WN;
    constexpr int MT  = WTM / 16;
    constexpr int NTT = WTN / 8;
    constexpr int RPP = THREADS / 2;
    constexpr int NLA = BM / RPP;
    constexpr int NLB = BN / RPP;
    constexpr int CHUNK = (MODE == 2) ? 32 : 16;

    __shared__ __align__(16) uint32_t As[2][BM][TLD];
    __shared__ __align__(16) uint32_t Bs[2][BN][TLD];
    __shared__ float sred[THREADS];

    const int tid  = threadIdx.x;
    const int lane = tid & 31;
    const int wid  = tid >> 5;
    const int wm   = wid / WN;
    const int wn   = wid % WN;

    const int lr = tid >> 1;
    const int ks = (tid & 1) * 8;   // element offset 0/8 within a k16
    const int js = ks >> 1;         // u32 pair offset 0/4
    const __half* Agh = Ah + (size_t)(bm + lr) * K + ks;
    // second stream: MODE1 -> lo residual array; MODE2 -> next k16 of A
    const __half* Agl = (MODE == 1) ? Al + (size_t)(bm + lr) * K + ks
                       : (MODE == 2) ? Agh + 16 : nullptr;
    const __half* Bg  = Bw + (size_t)(bn + lr) * K + ks;
    const __half* Bg2 = (MODE == 2) ? Bg + 16 : nullptr;

    float acc[MT][NTT][4];
#pragma unroll
    for (int i = 0; i < MT; i++)
#pragma unroll
        for (int j = 0; j < NTT; j++)
#pragma unroll
            for (int q = 0; q < 4; q++) acc[i][j][q] = 0.f;

    uint4 pah[NLA], pal[NLA], pbh[NLB], pbl[NLB];

#pragma unroll
    for (int l = 0; l < NLA; l++) {
        pah[l] = *(const uint4*)(Agh + (size_t)l * RPP * K);
        if (MODE >= 1) pal[l] = *(const uint4*)(Agl + (size_t)l * RPP * K);
    }
#pragma unroll
    for (int l = 0; l < NLB; l++) {
        pbh[l] = *(const uint4*)(Bg + (size_t)l * RPP * K);
        if (MODE == 2) pbl[l] = *(const uint4*)(Bg2 + (size_t)l * RPP * K);
    }

    auto store_tiles = [&](int buf) {
#pragma unroll
        for (int l = 0; l < NLA; l++) {
            *(uint4*)&As[buf][lr + l * RPP][js] = pah[l];
            if (MODE >= 1) *(uint4*)&As[buf][lr + l * RPP][8 + js] = pal[l];
        }
#pragma unroll
        for (int l = 0; l < NLB; l++) {
            *(uint4*)&Bs[buf][lr + l * RPP][js] = pbh[l];
            if (MODE == 2) *(uint4*)&Bs[buf][lr + l * RPP][8 + js] = pbl[l];
        }
    };

    store_tiles(0);
    __syncthreads();

    // ldmatrix per-thread base addresses
    const int lg8 = lane & 7;
    const int selA = (lane >> 3) & 1;
    const int selB = lane >> 4;
    const uint32_t aBase =
        (uint32_t)__cvta_generic_to_shared(&As[0][wm * WTM + selA * 8 + lg8][selB * 4]);
    const uint32_t bBase =
        (uint32_t)__cvta_generic_to_shared(&Bs[0][wn * WTN + selB * 8 + lg8][selA * 4]);
    constexpr uint32_t ABUF = BM * TLD * 4;
    constexpr uint32_t BBUF = BN * TLD * 4;
    constexpr uint32_t T16  = 16 * TLD * 4;

    const int nk = K / CHUNK;
    for (int kc = 0; kc < nk; kc++) {
        const int cur = kc & 1;
        if (kc + 1 < nk) {
            const int off = (kc + 1) * CHUNK;
#pragma unroll
            for (int l = 0; l < NLA; l++) {
                pah[l] = *(const uint4*)(Agh + (size_t)l * RPP * K + off);
                if (MODE >= 1) pal[l] = *(const uint4*)(Agl + (size_t)l * RPP * K + off);
            }
#pragma unroll
            for (int l = 0; l < NLB; l++) {
                pbh[l] = *(const uint4*)(Bg + (size_t)l * RPP * K + off);
                if (MODE == 2) pbl[l] = *(const uint4*)(Bg2 + (size_t)l * RPP * K + off);
            }
        }

        {
            const uint32_t aOff = aBase + (uint32_t)cur * ABUF;
            const uint32_t bOff = bBase + (uint32_t)cur * BBUF;
            uint32_t ah[MT][4], al[MT][4], bh[NTT][2], bl[NTT][2];
#pragma unroll
            for (int mt = 0; mt < MT; mt++) {
                ldsm_x4(ah[mt][0], ah[mt][1], ah[mt][2], ah[mt][3], aOff + mt * T16);
                if (MODE >= 1)
                    ldsm_x4(al[mt][0], al[mt][1], al[mt][2], al[mt][3],
                            aOff + mt * T16 + 8 * 4);
            }
#pragma unroll
            for (int p = 0; p < NTT / 2; p++) {
                ldsm_x4(bh[2*p][0], bh[2*p][1], bh[2*p+1][0], bh[2*p+1][1],
                        bOff + p * T16);
                if (MODE == 2)
                    ldsm_x4(bl[2*p][0], bl[2*p][1], bl[2*p+1][0], bl[2*p+1][1],
                            bOff + p * T16 + 8 * 4);
            }
#pragma unroll
            for (int mt = 0; mt < MT; mt++)
#pragma unroll
                for (int nt = 0; nt < NTT; nt++) {
                    mma_f16(acc[mt][nt][0], acc[mt][nt][1], acc[mt][nt][2], acc[mt][nt][3],
                            ah[mt][0], ah[mt][1], ah[mt][2], ah[mt][3],
                            bh[nt][0], bh[nt][1]);
                    if (MODE == 1)
                        mma_f16(acc[mt][nt][0], acc[mt][nt][1], acc[mt][nt][2], acc[mt][nt][3],
                                al[mt][0], al[mt][1], al[mt][2], al[mt][3],
                                bh[nt][0], bh[nt][1]);
                    else if (MODE == 2)
                        mma_f16(acc[mt][nt][0], acc[mt][nt][1], acc[mt][nt][2], acc[mt][nt][3],
                                al[mt][0], al[mt][1], al[mt][2], al[mt][3],
                                bl[nt][0], bl[nt][1]);
                }
        }

        if (kc + 1 < nk) store_tiles(cur ^ 1);
        __syncthreads();
    }

    // ---------------- epilogue ----------------
    float spsum = 0.f;
#pragma unroll
    for (int mt = 0; mt < MT; mt++) {
        int row = bm + wm * WTM + mt * 16 + (lane >> 2);
#pragma unroll
        for (int nt = 0; nt < NTT; nt++) {
            int col = bn + wn * WTN + nt * 8 + (lane & 3) * 2;
            float* a4 = acc[mt][nt];
            size_t i0 = (size_t)row * N + col;
            size_t i1 = (size_t)(row + 8) * N + col;
            float2 r0 = make_float2(a4[0], a4[1]);
            float2 r1 = make_float2(a4[2], a4[3]);
            if (EPI == 1) {
                float2 o0 = *(const float2*)(C + i0);
                float2 o1 = *(const float2*)(C + i1);
                r0.x += o0.x; r0.y += o0.y;
                r1.x += o1.x; r1.y += o1.y;
            } else if (EPI == 2) {
                r0.x = r0.x / (1.f + expf(-r0.x));
                r0.y = r0.y / (1.f + expf(-r0.y));
                r1.x = r1.x / (1.f + expf(-r1.x));
                r1.y = r1.y / (1.f + expf(-r1.y));
            } else if (EPI == 3) {
                float2 g0 = *(const float2*)(G + i0);
                float2 g1v = *(const float2*)(G + i1);
                r0.x *= g0.x; r0.y *= g0.y;
                r1.x *= g1v.x; r1.y *= g1v.y;
            } else if (EPI == 4) {
                spsum += softplusf(r0.x) + softplusf(r0.y) +
                         softplusf(r1.x) + softplusf(r1.y);
            } else if (EPI == 5) {
                int p = (col & 63) >> 1;
                {
                    float2 cs = g_rope[(row & (S_ - 1)) * 32 + p];
                    float xr = r0.x, xi = r0.y;
                    r0.x = xr * cs.x - xi * cs.y;
                    r0.y = xr * cs.y + xi * cs.x;
                }
                {
                    float2 cs = g_rope[((row + 8) & (S_ - 1)) * 32 + p];
                    float xr = r1.x, xi = r1.y;
                    r1.x = xr * cs.x - xi * cs.y;
                    r1.y = xr * cs.y + xi * cs.x;
                }
            }
            if (EPI == 3) {
                __half2 h0 = __floats2half2_rn(r0.x, r0.y);
                __half2 h1 = __floats2half2_rn(r1.x, r1.y);
                __half2 l0 = __floats2half2_rn(r0.x - __half2float(__low2half(h0)),
                                               r0.y - __half2float(__high2half(h0)));
                __half2 l1 = __floats2half2_rn(r1.x - __half2float(__low2half(h1)),
                                               r1.y - __half2float(__high2half(h1)));
                *(__half2*)(Oh + i0) = h0;
                *(__half2*)(Oh + i1) = h1;
                *(__half2*)(Ol + i0) = l0;
                *(__half2*)(Ol + i1) = l1;
            } else {
                *(float2*)(C + i0) = r0;
                *(float2*)(C + i1) = r1;
            }
        }
    }
    if (EPI == 4) {
        sred[tid] = spsum; __syncthreads();
        for (int st = THREADS / 2; st > 0; st >>= 1) {
            if (tid < st) sred[tid] += sred[tid + st];
            __syncthreads();
        }
        if (tid == 0) atomicAdd(&g_acc[0], (double)sred[0]);
    }
}

template<int BM, int BN, int WM, int WN, int EPI, int MODE>
__global__ __launch_bounds__(WM * WN * 32)
void gemm_f16(const __half* __restrict__ Ah, const __half* __restrict__ Al,
              const __half* __restrict__ Bw,
              float* __restrict__ C, const float* __restrict__ G,
              __half* __restrict__ Oh, __half* __restrict__ Ol, int N, int K) {
    gemm_f16_core<BM, BN, WM, WN, EPI, MODE>(Ah, Al, Bw, C, G, Oh, Ol, N, K,
                                             blockIdx.x * BM, blockIdx.y * BN);
}

// fused q/k/v (blockIdx.z selects weight/output); q,k get fused RoPE (EPI5); MODE2
__global__ __launch_bounds__(128)
void gemm_qkv_f16(const __half* __restrict__ Ah, int layer_off,
                  float* __restrict__ C0, float* __restrict__ C1, float* __restrict__ C2) {
    if (blockIdx.z == 0)
        gemm_f16_core<64, 64, 2, 2, 5, 2>(Ah, nullptr, g_wq + layer_off, C0, nullptr,
                                          nullptr, nullptr, D_, D_,
                                          blockIdx.x * 64, blockIdx.y * 64);
    else if (blockIdx.z == 1)
        gemm_f16_core<64, 64, 2, 2, 5, 2>(Ah, nullptr, g_wk + layer_off, C1, nullptr,
                                          nullptr, nullptr, D_, D_,
                                          blockIdx.x * 64, blockIdx.y * 64);
    else
        gemm_f16_core<64, 64, 2, 2, 0, 2>(Ah, nullptr, g_wv + layer_off, C2, nullptr,
                                          nullptr, nullptr, D_, D_,
                                          blockIdx.x * 64, blockIdx.y * 64);
}

// fused heads: z=0 -> logits (EPI0, w_out); z=1 -> c + softplus (EPI4, w_ctx); MODE2
__global__ __launch_bounds__(256)
void gemm_heads_f16(const __half* __restrict__ Ah,
                    float* __restrict__ Cout, float* __restrict__ Cc) {
    if (blockIdx.z == 0)
        gemm_f16_core<128, 128, 2, 4, 0, 2>(Ah, nullptr, g_wout, Cout, nullptr,
                                            nullptr, nullptr, V_, D_,
                                            blockIdx.x * 128, blockIdx.y * 128);
    else
        gemm_f16_core<128, 128, 2, 4, 4, 2>(Ah, nullptr, g_wctx, Cc, nullptr,
                                            nullptr, nullptr, V_, D_,
                                            blockIdx.x * 128, blockIdx.y * 128);
}

// ---------------- flash-style attention (writes o as fp16 hi) ----------------
__global__ __launch_bounds__(256)
void attn_flash() {
    const int qt = blockIdx.x;
    const int bh = blockIdx.y;
    const int b = bh / H_, h = bh - (bh / H_) * H_;
    const int tid = threadIdx.x;
    const int q  = tid >> 2;
    const int dg = (tid & 3) * 16;
    const int q0 = qt * 64;

    __shared__ float KS[64][68];
    __shared__ float Vs[64][68];
    __shared__ float rowm[64], rows[64], cfs[64];

    float4 qr[16];
    const float* qp = g_q + ((size_t)(b * S_ + q0 + q)) * D_ + h * HD_;
#pragma unroll
    for (int j = 0; j < 16; j++) qr[j] = *(const float4*)(qp + 4 * j);

    float acc[16];
#pragma unroll
    for (int j = 0; j < 16; j++) acc[j] = 0.f;
    if (tid < 64) { rowm[tid] = -1e30f; rows[tid] = 0.f; }

    for (int k0 = 0; k0 <= q0; k0 += 64) {
        {
            int r = tid >> 2, c = (tid & 3) * 16;
            const float* kp = g_k + ((size_t)(b * S_ + k0 + r)) * D_ + h * HD_ + c;
            const float* vp = g_v + ((size_t)(b * S_ + k0 + r)) * D_ + h * HD_ + c;
#pragma unroll
            for (int j = 0; j < 4; j++) {
                *(float4*)&KS[r][c + 4 * j] = *(const float4*)(kp + 4 * j);
                *(float4*)&Vs[r][c + 4 * j] = *(const float4*)(vp + 4 * j);
            }
        }
        __syncthreads();

        float sreg[16];
        {
            const int kb = (tid & 3) * 16;
#pragma unroll
            for (int j = 0; j < 16; j++) {
                int kk = kb + j;
                float d = 0.f;
#pragma unroll
                for (int t4 = 0; t4 < 16; t4++) {
                    float4 kv = *(const float4*)&KS[kk][4 * t4];
                    d += qr[t4].x * kv.x + qr[t4].y * kv.y +
                         qr[t4].z * kv.z + qr[t4].w * kv.w;
                }
                sreg[j] = (k0 + kk <= q0 + q) ? d * 0.125f : -1e30f;
            }
        }
        __syncthreads();

        {
            const int kb = (tid & 3) * 16;
#pragma unroll
            for (int j = 0; j < 16; j++) KS[q][kb + j] = sreg[j];
        }
        __syncthreads();

        if (tid < 64) {
            float mo = rowm[tid];
            float tm = mo;
#pragma unroll 8
            for (int kk = 0; kk < 64; kk++) tm = fmaxf(tm, KS[tid][kk]);
            float cf = expf(mo - tm);
            float ps = 0.f;
#pragma unroll 8
            for (int kk = 0; kk < 64; kk++) {
                float p = expf(KS[tid][kk] - tm);
                KS[tid][kk] = p;
                ps += p;
            }
            rowm[tid] = tm;
            rows[tid] = rows[tid] * cf + ps;
            cfs[tid] = cf;
        }
        __syncthreads();

        {
            float cf = cfs[q];
#pragma unroll
            for (int j = 0; j < 16; j++) acc[j] *= cf;
            for (int kk = 0; kk < 64; kk++) {
                float p = KS[q][kk];
#pragma unroll
                for (int j4 = 0; j4 < 4; j4++) {
                    float4 vv = *(const float4*)&Vs[kk][dg + 4 * j4];
                    acc[4 * j4 + 0] += p * vv.x;
                    acc[4 * j4 + 1] += p * vv.y;
                    acc[4 * j4 + 2] += p * vv.z;
                    acc[4 * j4 + 3] += p * vv.w;
                }
            }
        }
        __syncthreads();
    }

    float inv = 1.f / rows[q];
    size_t base = ((size_t)(b * S_ + q0 + q)) * D_ + h * HD_ + dg;
#pragma unroll
    for (int j2 = 0; j2 < 8; j2++) {
        float v0 = acc[2 * j2] * inv, v1 = acc[2 * j2 + 1] * inv;
        *(__half2*)(g_oh + base + 2 * j2) = __floats2half2_rn(v0, v1);
    }
}

// ---------------- sparse BCE correction ----------------
__global__ void corr_kernel(const int* __restrict__ y) {
    int s = blockIdx.x * blockDim.x + threadIdx.x;
    if (s >= S_) return;
    int tok[2][FCS_];
    for (int b = 0; b < 2; b++)
        for (int j = 0; j < FCS_; j++)
            tok[b][j] = y[b * YW_ + (FCS_ - 1) + ((s - (FCS_ - 1) + j + S_) & (S_ - 1))];
    double dsum = 0.0;
    for (int b = 0; b < 2; b++)
        for (int j = 0; j < FCS_; j++) {
            int v = tok[b][j];
            bool first = true;
            for (int b2 = 0; b2 <= b && first; b2++) {
                int jmax = (b2 == b) ? j : FCS_;
                for (int j2 = 0; j2 < jmax; j2++)
                    if (tok[b2][j2] == v) { first = false; break; }
            }
            if (!first) continue;
            int c0 = 0, c1 = 0;
            for (int j2 = 0; j2 < FCS_; j2++) {
                c0 += (tok[0][j2] == v);
                c1 += (tok[1][j2] == v);
            }
            float w = (c0 > 1 || c1 > 1) ? 1.5f : 1.0f;
            for (int b2 = 0; b2 < 2; b2++) {
                float cv = g_c[((size_t)(b2 * S_ + s)) * V_ + v];
                float t  = ((b2 == 0 ? c0 : c1) > 0) ? 1.f : 0.f;
                dsum += (double)((w - 1.f) * softplusf(cv) - w * t * cv);
            }
        }
    atomicAdd(&g_acc[1], dsum);
}

// ---------------- logits += exp-kernel context (ring-buffer window) ----
#define CTX_CHUNK 128
__global__ void ctx_scan_kernel(float* __restrict__ logits, const float* __restrict__ conv_w) {
    int v = blockIdx.x * blockDim.x + threadIdx.x;
    if (v >= V_) return;
    int b  = blockIdx.y;
    int s0 = blockIdx.z * CTX_CHUNK;
    float e = expf(-conv_w[0]);

    float pw[FCS_];
    pw[FCS_ - 1] = 1.f;
#pragma unroll
    for (int d = FCS_ - 1; d >= 1; --d) pw[d - 1] = pw[d] * e;

    float ring[FCS_];
#pragma unroll
    for (int j = 1; j <= FCS_; j++) {
        int sp = s0 - j;
        ring[(8 - j) & 7] = (sp >= 0) ? g_c[((size_t)(b * S_ + sp)) * V_ + v] : 0.f;
    }

    for (int t = 0; t < CTX_CHUNK / 8; t++) {
#pragma unroll
        for (int u = 0; u < 8; u++) {
            int s = s0 + 8 * t + u;
            size_t idx = ((size_t)(b * S_ + s)) * V_ + v;
            float ctx = 0.f;
#pragma unroll
            for (int d = 1; d <= FCS_; d++)
                ctx += pw[d - 1] * ring[(u - d) & 7];
            logits[idx] += ctx;
            ring[u] = g_c[idx];
        }
    }
}

// ---------------- NLL (one-pass online logsumexp) ----------------
__global__ void nll_kernel(const float* __restrict__ logits, const int* __restrict__ y) {
    int row = blockIdx.x;
    int b = row / S_, s = row - (row / S_) * S_;
    const float* lp = logits + (size_t)row * V_;
    __shared__ float rm[256], rs[256];
    float m = -1e30f, ssum = 0.f;
    for (int v = threadIdx.x; v < V_; v += 256) {
        float xv = lp[v];
        if (xv > m) { ssum = ssum * expf(m - xv) + 1.f; m = xv; }
        else        { ssum += expf(xv - m); }
    }
    rm[threadIdx.x] = m; rs[threadIdx.x] = ssum; __syncthreads();
    for (int st = 128; st > 0; st >>= 1) {
        if (threadIdx.x < st) {
            float m2 = rm[threadIdx.x + st], s2 = rs[threadIdx.x + st];
            float mm = fmaxf(rm[threadIdx.x], m2);
            rs[threadIdx.x] = rs[threadIdx.x] * expf(rm[threadIdx.x] - mm) +
                              s2 * expf(m2 - mm);
            rm[threadIdx.x] = mm;
        }
        __syncthreads();
    }
    if (threadIdx.x == 0) {
        int yt = y[b * YW_ + s];
        if (yt != -1) {
            float lse = rm[0] + logf(rs[0]);
            atomicAdd(&g_acc[2], (double)(lse - lp[yt]));
            atomicAdd(&g_acc[3], 1.0);
        }
    }
}

__global__ void finalize_kernel(float* __restrict__ out) {
    double cnt = g_acc[3] < 1.0 ? 1.0 : g_acc[3];
    out[(size_t)NT_ * V_]     = (float)(g_acc[2] / cnt);
    out[(size_t)NT_ * V_ + 1] = (float)((g_acc[0] + g_acc[1]) / ((double)NT_ * (double)V_));
}

// ---------------- launcher ----------------
extern "C" void kernel_launch(void* const* d_in, const int* in_sizes, int n_in,
                              void* d_out, int out_size) {
    const int*   x      = (const int*)  d_in[0];
    const int*   y      = (const int*)  d_in[1];
    const float* emb    = (const float*)d_in[2];
    const float* wq     = (const float*)d_in[3];
    const float* wk     = (const float*)d_in[4];
    const float* wv     = (const float*)d_in[5];
    const float* wo     = (const float*)d_in[6];
    const float* w1     = (const float*)d_in[7];
    const float* w2     = (const float*)d_in[8];
    const float* w3     = (const float*)d_in[9];
    const float* attn_n = (const float*)d_in[10];
    const float* ffn_n  = (const float*)d_in[11];
    const float* out_n  = (const float*)d_in[12];
    const float* w_out  = (const float*)d_in[13];
    const float* w_ctx  = (const float*)d_in[14];
    const float* conv_w = (const float*)d_in[15];
    float* out = (float*)d_out;

    float *h_, *q_, *k_, *v_, *g1_, *c_;
    __half *ah_, *al_, *oh_, *uh_, *ul_;
    __half *wq_f, *wk_f, *wv_f, *wo_f, *w1_f, *w3_f, *w2_f, *wout_f, *wctx_f;
    cudaGetSymbolAddress((void**)&h_,  g_h);
    cudaGetSymbolAddress((void**)&q_,  g_q);
    cudaGetSymbolAddress((void**)&k_,  g_k);
    cudaGetSymbolAddress((void**)&v_,  g_v);
    cudaGetSymbolAddress((void**)&g1_, g_g1);
    cudaGetSymbolAddress((void**)&c_,  g_c);
    cudaGetSymbolAddress((void**)&ah_, g_ah);
    cudaGetSymbolAddress((void**)&al_, g_al);
    cudaGetSymbolAddress((void**)&oh_, g_oh);
    cudaGetSymbolAddress((void**)&uh_, g_uh);
    cudaGetSymbolAddress((void**)&ul_, g_ul);
    cudaGetSymbolAddress((void**)&wq_f, g_wq);
    cudaGetSymbolAddress((void**)&wk_f, g_wk);
    cudaGetSymbolAddress((void**)&wv_f, g_wv);
    cudaGetSymbolAddress((void**)&wo_f, g_wo);
    cudaGetSymbolAddress((void**)&w1_f, g_w1);
    cudaGetSymbolAddress((void**)&w3_f, g_w3);
    cudaGetSymbolAddress((void**)&w2_f, g_w2);
    cudaGetSymbolAddress((void**)&wout_f, g_wout);
    cudaGetSymbolAddress((void**)&wctx_f, g_wctx);

    embed_kernel<<<(NT_ * D_ + 255) / 256, 256>>>(x, emb);

    // weight converts (fp32 -> fp16, MLP=4)
    {
        int nDD4 = L_ * D_ * D_ / 4;
        int nFD4 = L_ * F_ * D_ / 4;
        int nVD4 = V_ * D_ / 4;
        int gDD = (nDD4 + 1023) / 1024, gFD = (nFD4 + 1023) / 1024, gVD = (nVD4 + 1023) / 1024;
        wconv_kernel<<<gDD, 256>>>(wq, wq_f, nDD4);
        wconv_kernel<<<gDD, 256>>>(wk, wk_f, nDD4);
        wconv_kernel<<<gDD, 256>>>(wv, wv_f, nDD4);
        wconv_kernel<<<gDD, 256>>>(wo, wo_f, nDD4);
        wconv_kernel<<<gFD, 256>>>(w1, w1_f, nFD4);
        wconv_kernel<<<gFD, 256>>>(w3, w3_f, nFD4);
        wconv_kernel<<<gFD, 256>>>(w2, w2_f, nFD4);
        wconv_kernel<<<gVD, 256>>>(w_out, wout_f, nVD4);
        wconv_kernel<<<gVD, 256>>>(w_ctx, wctx_f, nVD4);
    }

    dim3 gQKV(NT_ / 64, D_ / 64, 3);     // 16 x 12 x 3 (64x64 tiles)
    dim3 gDs (NT_ / 64, D_ / 64);        // 16 x 12
    dim3 gF  (NT_ / 128, F_ / 64);       // 8 x 32 (128x64 tiles)
    dim3 gHD (NT_ / 128, V_ / 128, 2);   // 8 x 250 x 2 (fused heads)

    for (int i = 0; i < L_; i++) {
        int offDD = i * D_ * D_;
        int offFD = i * F_ * D_;

        // attn path: MODE2 (KT32, 1 mma/k16), rope fused into q/k epilogues
        rmsnorm_kernel<1><<<NT_, 256>>>(h_, attn_n + i * D_, ah_, nullptr);
        gemm_qkv_f16<<<gQKV, 128>>>(ah_, offDD, q_, k_, v_);
        attn_flash<<<dim3(S_ / 64, B_ * H_), 256>>>();
        gemm_f16<64, 64, 2, 2, 1, 2><<<gDs, 128>>>(oh_, nullptr, wo_f + offDD,
                                                   h_, nullptr, nullptr, nullptr, D_, D_);

        // ffn path: MODE1 (A-split fp16; only weights round)
        rmsnorm_kernel<2><<<NT_, 256>>>(h_, ffn_n + i * D_, ah_, al_);
        gemm_f16<128, 64, 2, 2, 2, 1><<<gF, 128>>>(ah_, al_, w1_f + offFD,
                                                   g1_, nullptr, nullptr, nullptr, F_, D_);
        gemm_f16<128, 64, 2, 2, 3, 1><<<gF, 128>>>(ah_, al_, w3_f + offFD,
                                                   nullptr, g1_, uh_, ul_, F_, D_);
        gemm_f16<64, 64, 2, 2, 1, 1><<<gDs, 128>>>(uh_, ul_, w2_f + offFD,
                                                   h_, nullptr, nullptr, nullptr, D_, F_);
    }

    // fused heads: MODE2 (KT32), one launch, 500 CTAs
    rmsnorm_kernel<1><<<NT_, 256>>>(h_, out_n, ah_, nullptr);
    gemm_heads_f16<<<gHD, 256>>>(ah_, out, c_);

    corr_kernel<<<(S_ + 255) / 256, 256>>>(y);
    ctx_scan_kernel<<<dim3((V_ + 255) / 256, B_, S_ / CTX_CHUNK), 256>>>(out, conv_w);
    nll_kernel<<<NT_, 256>>>(out, y);
    finalize_kernel<<<1, 1>>>(out);
}

// round 17
// speedup vs baseline: 1.1141x; 1.0605x over previous
#include <cuda_runtime.h>
#include <cuda_fp16.h>
#include <math.h>
#include <stdint.h>

#define B_  2
#define S_  512
#define V_  32000
#define D_  768
#define F_  2048
#define L_  4
#define H_  12
#define HD_ 64
#define FCS_ 8
#define YW_ (S_ + FCS_ - 1)   /* 519 */
#define NT_ (B_ * S_)         /* 1024 rows */

// ---------------- static scratch (allocation-free rule) ----------------
__device__ float  g_h [NT_ * D_];
__device__ float  g_q [NT_ * D_];
__device__ float  g_k [NT_ * D_];
__device__ float  g_v [NT_ * D_];
__device__ float  g_g1[NT_ * F_];
__device__ float  g_c [NT_ * V_];          // context head logits c (131 MB)
__device__ float2 g_rope[S_ * 32];
__device__ double g_acc[4];                // [0]=softplus [1]=delta [2]=nll [3]=valid

// fp16 activations (hi + lo residual where needed)
__device__ __align__(16) __half g_ah[NT_ * D_], g_al[NT_ * D_];
__device__ __align__(16) __half g_oh[NT_ * D_];
__device__ __align__(16) __half g_uh[NT_ * F_], g_ul[NT_ * F_];

// fp16 weights (converted once per launch)
__device__ __align__(16) __half g_wq[L_*D_*D_];
__device__ __align__(16) __half g_wk[L_*D_*D_];
__device__ __align__(16) __half g_wv[L_*D_*D_];
__device__ __align__(16) __half g_wo[L_*D_*D_];
__device__ __align__(16) __half g_w1[L_*F_*D_];
__device__ __align__(16) __half g_w3[L_*F_*D_];
__device__ __align__(16) __half g_w2[L_*D_*F_];
__device__ __align__(16) __half g_wout[V_*D_];
__device__ __align__(16) __half g_wctx[V_*D_];

__device__ __forceinline__ float softplusf(float x) {
    if (x > 15.0f) return x;
    return log1pf(expf(x));
}

__device__ __forceinline__ void mma_f16(float& c0, float& c1, float& c2, float& c3,
                                        uint32_t a0, uint32_t a1, uint32_t a2, uint32_t a3,
                                        uint32_t b0, uint32_t b1) {
    asm volatile("mma.sync.aligned.m16n8k16.row.col.f32.f16.f16.f32 "
                 "{%0,%1,%2,%3}, {%4,%5,%6,%7}, {%8,%9}, {%0,%1,%2,%3};"
                 : "+f"(c0), "+f"(c1), "+f"(c2), "+f"(c3)
                 : "r"(a0), "r"(a1), "r"(a2), "r"(a3), "r"(b0), "r"(b1));
}

__device__ __forceinline__ void ldsm_x4(uint32_t& r0, uint32_t& r1,
                                        uint32_t& r2, uint32_t& r3, uint32_t addr) {
    asm volatile("ldmatrix.sync.aligned.m8n8.x4.shared.b16 {%0,%1,%2,%3}, [%4];"
                 : "=r"(r0), "=r"(r1), "=r"(r2), "=r"(r3) : "r"(addr));
}

__device__ __forceinline__ void cp16(uint32_t dst, const void* src) {
    asm volatile("cp.async.cg.shared.global [%0], [%1], 16;" :: "r"(dst), "l"(src));
}
#define CP_COMMIT() asm volatile("cp.async.commit_group;" ::: "memory")
#define CP_WAIT0()  asm volatile("cp.async.wait_group 0;" ::: "memory")

// ---------------- ALL weight converts in one launch (grid-stride) ----------------
__global__ void wconv_all(const float* __restrict__ wq, const float* __restrict__ wk,
                          const float* __restrict__ wv, const float* __restrict__ wo,
                          const float* __restrict__ w1, const float* __restrict__ w3,
                          const float* __restrict__ w2,
                          const float* __restrict__ wout, const float* __restrict__ wctx) {
    constexpr long DD4 = (long)L_ * D_ * D_ / 4;
    constexpr long FD4 = (long)L_ * F_ * D_ / 4;
    constexpr long VD4 = (long)V_ * D_ / 4;
    constexpr long E0 = 4 * DD4, E1 = E0 + 3 * FD4, TOT = E1 + 2 * VD4;
    const long stride = (long)gridDim.x * blockDim.x;
    for (long i = (long)blockIdx.x * blockDim.x + threadIdx.x; i < TOT; i += stride) {
        const float* src; __half* dst; long off;
        if (i < E0) {
            int seg = (int)(i / DD4); off = i - (long)seg * DD4;
            src = (seg == 0) ? wq : (seg == 1) ? wk : (seg == 2) ? wv : wo;
            dst = (seg == 0) ? g_wq : (seg == 1) ? g_wk : (seg == 2) ? g_wv : g_wo;
        } else if (i < E1) {
            long j = i - E0; int seg = (int)(j / FD4); off = j - (long)seg * FD4;
            src = (seg == 0) ? w1 : (seg == 1) ? w3 : w2;
            dst = (seg == 0) ? g_w1 : (seg == 1) ? g_w3 : g_w2;
        } else {
            long j = i - E1; int seg = (int)(j / VD4); off = j - (long)seg * VD4;
            src = (seg == 0) ? wout : wctx;
            dst = (seg == 0) ? g_wout : g_wctx;
        }
        float4 v = ((const float4*)src)[off];
        ((__half2*)dst)[2 * off]     = __floats2half2_rn(v.x, v.y);
        ((__half2*)dst)[2 * off + 1] = __floats2half2_rn(v.z, v.w);
    }
}

// ---------------- embedding gather (+ acc zero + rope table fold-in) ----------
__global__ void embed_kernel(const int* __restrict__ x, const float* __restrict__ emb) {
    int i = blockIdx.x * blockDim.x + threadIdx.x;
    if (i < 4) g_acc[i] = 0.0;
    if (i < S_ * 32) {
        int s = i / 32, p = i - (i / 32) * 32;
        float f   = expf((float)(2 * p) * (-logf(10000.0f) / (float)HD_));
        float ang = (float)s * f;
        double a  = (double)ang;
        g_rope[i] = make_float2((float)cos(a), (float)sin(a));
    }
    if (i >= NT_ * D_) return;
    int row = i / D_;
    int d   = i - row * D_;
    g_h[i] = emb[(size_t)x[row] * D_ + d];
}

// ---------------- rmsnorm (SPLIT: 1=fp16 hi only, 2=fp16 hi+lo) ----------------
template<int SPLIT>
__global__ void rmsnorm_kernel(const float* __restrict__ in, const float* __restrict__ w,
                               __half* __restrict__ oh, __half* __restrict__ ol) {
    int row = blockIdx.x;
    const float* ip = in + row * D_;
    __shared__ float red[256];
    float ss = 0.f;
    for (int d = threadIdx.x; d < D_; d += 256) { float v = ip[d]; ss += v * v; }
    red[threadIdx.x] = ss; __syncthreads();
    for (int st = 128; st > 0; st >>= 1) {
        if (threadIdx.x < st) red[threadIdx.x] += red[threadIdx.x + st];
        __syncthreads();
    }
    float rs = rsqrtf(red[0] / (float)D_ + 1e-5f);
    for (int d = threadIdx.x; d < D_; d += 256) {
        float v = ip[d] * rs * w[d];
        __half h = __float2half_rn(v);
        oh[row * D_ + d] = h;
        if (SPLIT == 2) ol[row * D_ + d] = __float2half_rn(v - __half2float(h));
    }
}

#define TLD 20   /* smem row stride (u32): conflict-free for ldmatrix (8 rows x 16B) */

// =======================================================================
//  fp16 NT-GEMM with cp.async double-buffered pipeline.
//  MODE 0: KT16, A=hi (1 mma/k16)
//  MODE 1: KT16, A=hi+lo residual (2 mma/k16, same k)      [FFN]
//  MODE 2: KT32, two k16 sub-chunks per buffer (bitwise == MODE0 order)
//  EPI: 0=store 1=add 2=silu 3=mulG->fp16 hi/lo 4=store+softplus 5=rope-store
// =======================================================================
template<int BM, int BN, int WM, int WN, int EPI, int MODE>
__device__ __forceinline__ void gemm_f16_core(const __half* __restrict__ Ah,
                                              const __half* __restrict__ Al,
                                              const __half* __restrict__ Bw,
                                              float* __restrict__ C,
                                              const float* __restrict__ G,
                                              __half* __restrict__ Oh,
                                              __half* __restrict__ Ol,
                                              int N, int K, int bm, int bn) {
    constexpr int THREADS = WM * WN * 32;
    constexpr int WTM = BM / WM;
    constexpr int WTN = BN / WN;
    constexpr int MT  = WTM / 16;
    constexpr int NTT = WTN / 8;
    constexpr int RPP = THREADS / 2;
    constexpr int NLA = BM / RPP;
    constexpr int NLB = BN / RPP;
    constexpr int CHUNK = (MODE == 2) ? 32 : 16;

    __shared__ __align__(16) uint32_t As[2][BM][TLD];
    __shared__ __align__(16) uint32_t Bs[2][BN][TLD];
    __shared__ float sred[THREADS];

    const int tid  = threadIdx.x;
    const int lane = tid & 31;
    const int wid  = tid >> 5;
    const int wm   = wid / WN;
    const int wn   = wid % WN;

    const int lr = tid >> 1;
    const int ks = (tid & 1) * 8;   // element offset 0/8 within a k16
    const int js = ks >> 1;         // u32 pair offset 0/4
    const __half* Agh = Ah + (size_t)(bm + lr) * K + ks;
    const __half* Agl = (MODE == 1) ? Al + (size_t)(bm + lr) * K + ks
                       : (MODE == 2) ? Agh + 16 : nullptr;
    const __half* Bg  = Bw + (size_t)(bn + lr) * K + ks;
    const __half* Bg2 = (MODE == 2) ? Bg + 16 : nullptr;

    float acc[MT][NTT][4];
#pragma unroll
    for (int i = 0; i < MT; i++)
#pragma unroll
        for (int j = 0; j < NTT; j++)
#pragma unroll
            for (int q = 0; q < 4; q++) acc[i][j][q] = 0.f;

    constexpr uint32_t ABUF = BM * TLD * 4;
    constexpr uint32_t BBUF = BN * TLD * 4;
    constexpr uint32_t T16  = 16 * TLD * 4;

    const uint32_t sA0 = (uint32_t)__cvta_generic_to_shared(&As[0][lr][js]);
    const uint32_t sB0 = (uint32_t)__cvta_generic_to_shared(&Bs[0][lr][js]);

    auto prefetch = [&](int kc, int buf) {
        const int off = kc * CHUNK;
        const uint32_t aB = sA0 + (uint32_t)buf * ABUF;
        const uint32_t bB = sB0 + (uint32_t)buf * BBUF;
#pragma unroll
        for (int l = 0; l < NLA; l++) {
            cp16(aB + l * RPP * TLD * 4, Agh + (size_t)l * RPP * K + off);
            if (MODE >= 1)
                cp16(aB + l * RPP * TLD * 4 + 32, Agl + (size_t)l * RPP * K + off);
        }
#pragma unroll
        for (int l = 0; l < NLB; l++) {
            cp16(bB + l * RPP * TLD * 4, Bg + (size_t)l * RPP * K + off);
            if (MODE == 2)
                cp16(bB + l * RPP * TLD * 4 + 32, Bg2 + (size_t)l * RPP * K + off);
        }
        CP_COMMIT();
    };

    // ldmatrix per-thread base addresses
    const int lg8 = lane & 7;
    const int selA = (lane >> 3) & 1;
    const int selB = lane >> 4;
    const uint32_t aBase =
        (uint32_t)__cvta_generic_to_shared(&As[0][wm * WTM + selA * 8 + lg8][selB * 4]);
    const uint32_t bBase =
        (uint32_t)__cvta_generic_to_shared(&Bs[0][wn * WTN + selB * 8 + lg8][selA * 4]);

    prefetch(0, 0);

    const int nk = K / CHUNK;
    for (int kc = 0; kc < nk; kc++) {
        const int cur = kc & 1;
        CP_WAIT0();
        __syncthreads();
        if (kc + 1 < nk) prefetch(kc + 1, cur ^ 1);

        {
            const uint32_t aOff = aBase + (uint32_t)cur * ABUF;
            const uint32_t bOff = bBase + (uint32_t)cur * BBUF;
            uint32_t ah[MT][4], al[MT][4], bh[NTT][2], bl[NTT][2];
#pragma unroll
            for (int mt = 0; mt < MT; mt++) {
                ldsm_x4(ah[mt][0], ah[mt][1], ah[mt][2], ah[mt][3], aOff + mt * T16);
                if (MODE >= 1)
                    ldsm_x4(al[mt][0], al[mt][1], al[mt][2], al[mt][3],
                            aOff + mt * T16 + 8 * 4);
            }
#pragma unroll
            for (int p = 0; p < NTT / 2; p++) {
                ldsm_x4(bh[2*p][0], bh[2*p][1], bh[2*p+1][0], bh[2*p+1][1],
                        bOff + p * T16);
                if (MODE == 2)
                    ldsm_x4(bl[2*p][0], bl[2*p][1], bl[2*p+1][0], bl[2*p+1][1],
                            bOff + p * T16 + 8 * 4);
            }
#pragma unroll
            for (int mt = 0; mt < MT; mt++)
#pragma unroll
                for (int nt = 0; nt < NTT; nt++) {
                    mma_f16(acc[mt][nt][0], acc[mt][nt][1], acc[mt][nt][2], acc[mt][nt][3],
                            ah[mt][0], ah[mt][1], ah[mt][2], ah[mt][3],
                            bh[nt][0], bh[nt][1]);
                    if (MODE == 1)
                        mma_f16(acc[mt][nt][0], acc[mt][nt][1], acc[mt][nt][2], acc[mt][nt][3],
                                al[mt][0], al[mt][1], al[mt][2], al[mt][3],
                                bh[nt][0], bh[nt][1]);
                    else if (MODE == 2)
                        mma_f16(acc[mt][nt][0], acc[mt][nt][1], acc[mt][nt][2], acc[mt][nt][3],
                                al[mt][0], al[mt][1], al[mt][2], al[mt][3],
                                bl[nt][0], bl[nt][1]);
                }
        }
    }

    // ---------------- epilogue ----------------
    float spsum = 0.f;
#pragma unroll
    for (int mt = 0; mt < MT; mt++) {
        int row = bm + wm * WTM + mt * 16 + (lane >> 2);
#pragma unroll
        for (int nt = 0; nt < NTT; nt++) {
            int col = bn + wn * WTN + nt * 8 + (lane & 3) * 2;
            float* a4 = acc[mt][nt];
            size_t i0 = (size_t)row * N + col;
            size_t i1 = (size_t)(row + 8) * N + col;
            float2 r0 = make_float2(a4[0], a4[1]);
            float2 r1 = make_float2(a4[2], a4[3]);
            if (EPI == 1) {
                float2 o0 = *(const float2*)(C + i0);
                float2 o1 = *(const float2*)(C + i1);
                r0.x += o0.x; r0.y += o0.y;
                r1.x += o1.x; r1.y += o1.y;
            } else if (EPI == 2) {
                r0.x = r0.x / (1.f + expf(-r0.x));
                r0.y = r0.y / (1.f + expf(-r0.y));
                r1.x = r1.x / (1.f + expf(-r1.x));
                r1.y = r1.y / (1.f + expf(-r1.y));
            } else if (EPI == 3) {
                float2 g0 = *(const float2*)(G + i0);
                float2 g1v = *(const float2*)(G + i1);
                r0.x *= g0.x; r0.y *= g0.y;
                r1.x *= g1v.x; r1.y *= g1v.y;
            } else if (EPI == 4) {
                spsum += softplusf(r0.x) + softplusf(r0.y) +
                         softplusf(r1.x) + softplusf(r1.y);
            } else if (EPI == 5) {
                int p = (col & 63) >> 1;
                {
                    float2 cs = g_rope[(row & (S_ - 1)) * 32 + p];
                    float xr = r0.x, xi = r0.y;
                    r0.x = xr * cs.x - xi * cs.y;
                    r0.y = xr * cs.y + xi * cs.x;
                }
                {
                    float2 cs = g_rope[((row + 8) & (S_ - 1)) * 32 + p];
                    float xr = r1.x, xi = r1.y;
                    r1.x = xr * cs.x - xi * cs.y;
                    r1.y = xr * cs.y + xi * cs.x;
                }
            }
            if (EPI == 3) {
                __half2 h0 = __floats2half2_rn(r0.x, r0.y);
                __half2 h1 = __floats2half2_rn(r1.x, r1.y);
                __half2 l0 = __floats2half2_rn(r0.x - __half2float(__low2half(h0)),
                                               r0.y - __half2float(__high2half(h0)));
                __half2 l1 = __floats2half2_rn(r1.x - __half2float(__low2half(h1)),
                                               r1.y - __half2float(__high2half(h1)));
                *(__half2*)(Oh + i0) = h0;
                *(__half2*)(Oh + i1) = h1;
                *(__half2*)(Ol + i0) = l0;
                *(__half2*)(Ol + i1) = l1;
            } else {
                *(float2*)(C + i0) = r0;
                *(float2*)(C + i1) = r1;
            }
        }
    }
    if (EPI == 4) {
        sred[tid] = spsum; __syncthreads();
        for (int st = THREADS / 2; st > 0; st >>= 1) {
            if (tid < st) sred[tid] += sred[tid + st];
            __syncthreads();
        }
        if (tid == 0) atomicAdd(&g_acc[0], (double)sred[0]);
    }
}

template<int BM, int BN, int WM, int WN, int EPI, int MODE>
__global__ __launch_bounds__(WM * WN * 32)
void gemm_f16(const __half* __restrict__ Ah, const __half* __restrict__ Al,
              const __half* __restrict__ Bw,
              float* __restrict__ C, const float* __restrict__ G,
              __half* __restrict__ Oh, __half* __restrict__ Ol, int N, int K) {
    gemm_f16_core<BM, BN, WM, WN, EPI, MODE>(Ah, Al, Bw, C, G, Oh, Ol, N, K,
                                             blockIdx.x * BM, blockIdx.y * BN);
}

// fused q/k/v (blockIdx.z selects weight/output); q,k get fused RoPE (EPI5); MODE2
__global__ __launch_bounds__(128)
void gemm_qkv_f16(const __half* __restrict__ Ah, int layer_off,
                  float* __restrict__ C0, float* __restrict__ C1, float* __restrict__ C2) {
    if (blockIdx.z == 0)
        gemm_f16_core<64, 64, 2, 2, 5, 2>(Ah, nullptr, g_wq + layer_off, C0, nullptr,
                                          nullptr, nullptr, D_, D_,
                                          blockIdx.x * 64, blockIdx.y * 64);
    else if (blockIdx.z == 1)
        gemm_f16_core<64, 64, 2, 2, 5, 2>(Ah, nullptr, g_wk + layer_off, C1, nullptr,
                                          nullptr, nullptr, D_, D_,
                                          blockIdx.x * 64, blockIdx.y * 64);
    else
        gemm_f16_core<64, 64, 2, 2, 0, 2>(Ah, nullptr, g_wv + layer_off, C2, nullptr,
                                          nullptr, nullptr, D_, D_,
                                          blockIdx.x * 64, blockIdx.y * 64);
}

// fused heads: z=0 -> logits (EPI0, w_out); z=1 -> c + softplus (EPI4, w_ctx); MODE2
__global__ __launch_bounds__(256)
void gemm_heads_f16(const __half* __restrict__ Ah,
                    float* __restrict__ Cout, float* __restrict__ Cc) {
    if (blockIdx.z == 0)
        gemm_f16_core<128, 128, 2, 4, 0, 2>(Ah, nullptr, g_wout, Cout, nullptr,
                                            nullptr, nullptr, V_, D_,
                                            blockIdx.x * 128, blockIdx.y * 128);
    else
        gemm_f16_core<128, 128, 2, 4, 4, 2>(Ah, nullptr, g_wctx, Cc, nullptr,
                                            nullptr, nullptr, V_, D_,
                                            blockIdx.x * 128, blockIdx.y * 128);
}

// ---------------- flash-style attention (writes o as fp16 hi) ----------------
__global__ __launch_bounds__(256)
void attn_flash() {
    const int qt = blockIdx.x;
    const int bh = blockIdx.y;
    const int b = bh / H_, h = bh - (bh / H_) * H_;
    const int tid = threadIdx.x;
    const int q  = tid >> 2;
    const int dg = (tid & 3) * 16;
    const int q0 = qt * 64;

    __shared__ float KS[64][68];
    __shared__ float Vs[64][68];
    __shared__ float rowm[64], rows[64], cfs[64];

    float4 qr[16];
    const float* qp = g_q + ((size_t)(b * S_ + q0 + q)) * D_ + h * HD_;
#pragma unroll
    for (int j = 0; j < 16; j++) qr[j] = *(const float4*)(qp + 4 * j);

    float acc[16];
#pragma unroll
    for (int j = 0; j < 16; j++) acc[j] = 0.f;
    if (tid < 64) { rowm[tid] = -1e30f; rows[tid] = 0.f; }

    for (int k0 = 0; k0 <= q0; k0 += 64) {
        {
            int r = tid >> 2, c = (tid & 3) * 16;
            const float* kp = g_k + ((size_t)(b * S_ + k0 + r)) * D_ + h * HD_ + c;
            const float* vp = g_v + ((size_t)(b * S_ + k0 + r)) * D_ + h * HD_ + c;
#pragma unroll
            for (int j = 0; j < 4; j++) {
                *(float4*)&KS[r][c + 4 * j] = *(const float4*)(kp + 4 * j);
                *(float4*)&Vs[r][c + 4 * j] = *(const float4*)(vp + 4 * j);
            }
        }
        __syncthreads();

        float sreg[16];
        {
            const int kb = (tid & 3) * 16;
#pragma unroll
            for (int j = 0; j < 16; j++) {
                int kk = kb + j;
                float d = 0.f;
#pragma unroll
                for (int t4 = 0; t4 < 16; t4++) {
                    float4 kv = *(const float4*)&KS[kk][4 * t4];
                    d += qr[t4].x * kv.x + qr[t4].y * kv.y +
                         qr[t4].z * kv.z + qr[t4].w * kv.w;
                }
                sreg[j] = (k0 + kk <= q0 + q) ? d * 0.125f : -1e30f;
            }
        }
        __syncthreads();

        {
            const int kb = (tid & 3) * 16;
#pragma unroll
            for (int j = 0; j < 16; j++) KS[q][kb + j] = sreg[j];
        }
        __syncthreads();

        if (tid < 64) {
            float mo = rowm[tid];
            float tm = mo;
#pragma unroll 8
            for (int kk = 0; kk < 64; kk++) tm = fmaxf(tm, KS[tid][kk]);
            float cf = expf(mo - tm);
            float ps = 0.f;
#pragma unroll 8
            for (int kk = 0; kk < 64; kk++) {
                float p = expf(KS[tid][kk] - tm);
                KS[tid][kk] = p;
                ps += p;
            }
            rowm[tid] = tm;
            rows[tid] = rows[tid] * cf + ps;
            cfs[tid] = cf;
        }
        __syncthreads();

        {
            float cf = cfs[q];
#pragma unroll
            for (int j = 0; j < 16; j++) acc[j] *= cf;
            for (int kk = 0; kk < 64; kk++) {
                float p = KS[q][kk];
#pragma unroll
                for (int j4 = 0; j4 < 4; j4++) {
                    float4 vv = *(const float4*)&Vs[kk][dg + 4 * j4];
                    acc[4 * j4 + 0] += p * vv.x;
                    acc[4 * j4 + 1] += p * vv.y;
                    acc[4 * j4 + 2] += p * vv.z;
                    acc[4 * j4 + 3] += p * vv.w;
                }
            }
        }
        __syncthreads();
    }

    float inv = 1.f / rows[q];
    size_t base = ((size_t)(b * S_ + q0 + q)) * D_ + h * HD_ + dg;
#pragma unroll
    for (int j2 = 0; j2 < 8; j2++) {
        float v0 = acc[2 * j2] * inv, v1 = acc[2 * j2 + 1] * inv;
        *(__half2*)(g_oh + base + 2 * j2) = __floats2half2_rn(v0, v1);
    }
}

// ---------------- sparse BCE correction ----------------
__global__ void corr_kernel(const int* __restrict__ y) {
    int s = blockIdx.x * blockDim.x + threadIdx.x;
    if (s >= S_) return;
    int tok[2][FCS_];
    for (int b = 0; b < 2; b++)
        for (int j = 0; j < FCS_; j++)
            tok[b][j] = y[b * YW_ + (FCS_ - 1) + ((s - (FCS_ - 1) + j + S_) & (S_ - 1))];
    double dsum = 0.0;
    for (int b = 0; b < 2; b++)
        for (int j = 0; j < FCS_; j++) {
            int v = tok[b][j];
            bool first = true;
            for (int b2 = 0; b2 <= b && first; b2++) {
                int jmax = (b2 == b) ? j : FCS_;
                for (int j2 = 0; j2 < jmax; j2++)
                    if (tok[b2][j2] == v) { first = false; break; }
            }
            if (!first) continue;
            int c0 = 0, c1 = 0;
            for (int j2 = 0; j2 < FCS_; j2++) {
                c0 += (tok[0][j2] == v);
                c1 += (tok[1][j2] == v);
            }
            float w = (c0 > 1 || c1 > 1) ? 1.5f : 1.0f;
            for (int b2 = 0; b2 < 2; b2++) {
                float cv = g_c[((size_t)(b2 * S_ + s)) * V_ + v];
                float t  = ((b2 == 0 ? c0 : c1) > 0) ? 1.f : 0.f;
                dsum += (double)((w - 1.f) * softplusf(cv) - w * t * cv);
            }
        }
    atomicAdd(&g_acc[1], dsum);
}

// ---------------- logits += exp-kernel context (ring-buffer window) ----
#define CTX_CHUNK 128
__global__ void ctx_scan_kernel(float* __restrict__ logits, const float* __restrict__ conv_w) {
    int v = blockIdx.x * blockDim.x + threadIdx.x;
    if (v >= V_) return;
    int b  = blockIdx.y;
    int s0 = blockIdx.z * CTX_CHUNK;
    float e = expf(-conv_w[0]);

    float pw[FCS_];
    pw[FCS_ - 1] = 1.f;
#pragma unroll
    for (int d = FCS_ - 1; d >= 1; --d) pw[d - 1] = pw[d] * e;

    float ring[FCS_];
#pragma unroll
    for (int j = 1; j <= FCS_; j++) {
        int sp = s0 - j;
        ring[(8 - j) & 7] = (sp >= 0) ? g_c[((size_t)(b * S_ + sp)) * V_ + v] : 0.f;
    }

    for (int t = 0; t < CTX_CHUNK / 8; t++) {
#pragma unroll
        for (int u = 0; u < 8; u++) {
            int s = s0 + 8 * t + u;
            size_t idx = ((size_t)(b * S_ + s)) * V_ + v;
            float ctx = 0.f;
#pragma unroll
            for (int d = 1; d <= FCS_; d++)
                ctx += pw[d - 1] * ring[(u - d) & 7];
            logits[idx] += ctx;
            ring[u] = g_c[idx];
        }
    }
}

// ---------------- NLL (one-pass online logsumexp) ----------------
__global__ void nll_kernel(const float* __restrict__ logits, const int* __restrict__ y) {
    int row = blockIdx.x;
    int b = row / S_, s = row - (row / S_) * S_;
    const float* lp = logits + (size_t)row * V_;
    __shared__ float rm[256], rs[256];
    float m = -1e30f, ssum = 0.f;
    for (int v = threadIdx.x; v < V_; v += 256) {
        float xv = lp[v];
        if (xv > m) { ssum = ssum * expf(m - xv) + 1.f; m = xv; }
        else        { ssum += expf(xv - m); }
    }
    rm[threadIdx.x] = m; rs[threadIdx.x] = ssum; __syncthreads();
    for (int st = 128; st > 0; st >>= 1) {
        if (threadIdx.x < st) {
            float m2 = rm[threadIdx.x + st], s2 = rs[threadIdx.x + st];
            float mm = fmaxf(rm[threadIdx.x], m2);
            rs[threadIdx.x] = rs[threadIdx.x] * expf(rm[threadIdx.x] - mm) +
                              s2 * expf(m2 - mm);
            rm[threadIdx.x] = mm;
        }
        __syncthreads();
    }
    if (threadIdx.x == 0) {
        int yt = y[b * YW_ + s];
        if (yt != -1) {
            float lse = rm[0] + logf(rs[0]);
            atomicAdd(&g_acc[2], (double)(lse - lp[yt]));
            atomicAdd(&g_acc[3], 1.0);
        }
    }
}

__global__ void finalize_kernel(float* __restrict__ out) {
    double cnt = g_acc[3] < 1.0 ? 1.0 : g_acc[3];
    out[(size_t)NT_ * V_]     = (float)(g_acc[2] / cnt);
    out[(size_t)NT_ * V_ + 1] = (float)((g_acc[0] + g_acc[1]) / ((double)NT_ * (double)V_));
}

// ---------------- launcher ----------------
extern "C" void kernel_launch(void* const* d_in, const int* in_sizes, int n_in,
                              void* d_out, int out_size) {
    const int*   x      = (const int*)  d_in[0];
    const int*   y      = (const int*)  d_in[1];
    const float* emb    = (const float*)d_in[2];
    const float* wq     = (const float*)d_in[3];
    const float* wk     = (const float*)d_in[4];
    const float* wv     = (const float*)d_in[5];
    const float* wo     = (const float*)d_in[6];
    const float* w1     = (const float*)d_in[7];
    const float* w2     = (const float*)d_in[8];
    const float* w3     = (const float*)d_in[9];
    const float* attn_n = (const float*)d_in[10];
    const float* ffn_n  = (const float*)d_in[11];
    const float* out_n  = (const float*)d_in[12];
    const float* w_out  = (const float*)d_in[13];
    const float* w_ctx  = (const float*)d_in[14];
    const float* conv_w = (const float*)d_in[15];
    float* out = (float*)d_out;

    float *h_, *q_, *k_, *v_, *g1_, *c_;
    __half *ah_, *al_, *oh_, *uh_, *ul_;
    __half *wo_f, *w1_f, *w3_f, *w2_f;
    cudaGetSymbolAddress((void**)&h_,  g_h);
    cudaGetSymbolAddress((void**)&q_,  g_q);
    cudaGetSymbolAddress((void**)&k_,  g_k);
    cudaGetSymbolAddress((void**)&v_,  g_v);
    cudaGetSymbolAddress((void**)&g1_, g_g1);
    cudaGetSymbolAddress((void**)&c_,  g_c);
    cudaGetSymbolAddress((void**)&ah_, g_ah);
    cudaGetSymbolAddress((void**)&al_, g_al);
    cudaGetSymbolAddress((void**)&oh_, g_oh);
    cudaGetSymbolAddress((void**)&uh_, g_uh);
    cudaGetSymbolAddress((void**)&ul_, g_ul);
    cudaGetSymbolAddress((void**)&wo_f, g_wo);
    cudaGetSymbolAddress((void**)&w1_f, g_w1);
    cudaGetSymbolAddress((void**)&w3_f, g_w3);
    cudaGetSymbolAddress((void**)&w2_f, g_w2);

    embed_kernel<<<(NT_ * D_ + 255) / 256, 256>>>(x, emb);
    wconv_all<<<1024, 256>>>(wq, wk, wv, wo, w1, w3, w2, w_out, w_ctx);

    dim3 gQKV(NT_ / 64, D_ / 64, 3);     // 16 x 12 x 3 (64x64 tiles)
    dim3 gDs (NT_ / 64, D_ / 64);        // 16 x 12
    dim3 gF  (NT_ / 128, F_ / 64);       // 8 x 32 (128x64 tiles)
    dim3 gHD (NT_ / 128, V_ / 128, 2);   // 8 x 250 x 2 (fused heads)

    for (int i = 0; i < L_; i++) {
        int offDD = i * D_ * D_;
        int offFD = i * F_ * D_;

        // attn path: MODE2 (KT32, 1 mma/k16), rope fused into q/k epilogues
        rmsnorm_kernel<1><<<NT_, 256>>>(h_, attn_n + i * D_, ah_, nullptr);
        gemm_qkv_f16<<<gQKV, 128>>>(ah_, offDD, q_, k_, v_);
        attn_flash<<<dim3(S_ / 64, B_ * H_), 256>>>();
        gemm_f16<64, 64, 2, 2, 1, 2><<<gDs, 128>>>(oh_, nullptr, wo_f + offDD,
                                                   h_, nullptr, nullptr, nullptr, D_, D_);

        // ffn path: MODE1 (A-split fp16; only weights round)
        rmsnorm_kernel<2><<<NT_, 256>>>(h_, ffn_n + i * D_, ah_, al_);
        gemm_f16<128, 64, 2, 2, 2, 1><<<gF, 128>>>(ah_, al_, w1_f + offFD,
                                                   g1_, nullptr, nullptr, nullptr, F_, D_);
        gemm_f16<128, 64, 2, 2, 3, 1><<<gF, 128>>>(ah_, al_, w3_f + offFD,
                                                   nullptr, g1_, uh_, ul_, F_, D_);
        gemm_f16<64, 64, 2, 2, 1, 1><<<gDs, 128>>>(uh_, ul_, w2_f + offFD,
                                                   h_, nullptr, nullptr, nullptr, D_, F_);
    }

    // fused heads: MODE2 (KT32), one launch, 500 CTAs
    rmsnorm_kernel<1><<<NT_, 256>>>(h_, out_n, ah_, nullptr);
    gemm_heads_f16<<<gHD, 256>>>(ah_, out, c_);

    corr_kernel<<<(S_ + 255) / 256, 256>>>(y);
    ctx_scan_kernel<<<dim3((V_ + 255) / 256, B_, S_ / CTX_CHUNK), 256>>>(out, conv_w);
    nll_kernel<<<NT_, 256>>>(out, y);
    finalize_kernel<<<1, 1>>>(out);
}